// round 2
// baseline (speedup 1.0000x reference)
#include <cuda_runtime.h>
#include <math.h>
#include <stdint.h>

// Problem constants
#define B_   8
#define S_   1024
#define ID_  1024
#define OD_  1024
#define H_   16
#define HD_  64
#define M_   (B_ * S_)          // 8192 rows
#define KHALF 7                 // KSIZE//2, band = [i-7, i+7]

// Scratch (device globals; no allocation allowed)
__device__ float g_q[(size_t)B_ * S_ * OD_];   // m_trans[..., :ODIM]
__device__ float g_v[(size_t)B_ * S_ * OD_];   // m_trans[..., ODIM:]
__device__ float g_k[(size_t)B_ * S_ * OD_];   // m_feats @ Wv
__device__ float g_vsum[B_ * OD_];             // sum over seq of v (for all-masked rows)

// ---------------------------------------------------------------------------
// GEMM: C = A[8192,1024] @ W + bias, fused over 3 destinations (q, v, k).
// Block tiles 128x128, BK=8, 256 threads, 8x8 per-thread microtile.
// Grid: (24, 64). N-tiles 0..7 -> q (Wc cols 0..1023), 8..15 -> v (Wc cols
// 1024..2047), 16..23 -> k (Wv).
// ---------------------------------------------------------------------------
__global__ __launch_bounds__(256) void gemm_qkv(
    const float* __restrict__ A,
    const float* __restrict__ Wc, const float* __restrict__ bc,
    const float* __restrict__ Wv, const float* __restrict__ bv)
{
    const int K = ID_;
    int bn = blockIdx.x, bm = blockIdx.y;

    const float* Bmat; int ldb; const float* bias; float* C; int wcol0, ccol0;
    if (bn < 16) {
        Bmat = Wc; ldb = 2 * OD_; bias = bc; wcol0 = bn * 128;
        if (bn < 8) { C = g_q; ccol0 = wcol0; }
        else        { C = g_v; ccol0 = wcol0 - OD_; }
    } else {
        Bmat = Wv; ldb = OD_; bias = bv; wcol0 = (bn - 16) * 128; C = g_k; ccol0 = wcol0;
    }

    __shared__ float As[8][128];   // transposed: As[k][m]
    __shared__ float Bs[8][128];   // Bs[k][n]

    int tid  = threadIdx.x;
    int arow = tid >> 1;            // 0..127
    int acol = (tid & 1) * 4;       // 0 or 4
    int brow = tid >> 5;            // 0..7
    int bcol = (tid & 31) * 4;      // 0..124
    int tr   = (tid >> 4) * 8;      // thread row base in tile
    int tc   = (tid & 15) * 8;      // thread col base in tile

    float acc[8][8];
#pragma unroll
    for (int i = 0; i < 8; i++)
#pragma unroll
        for (int j = 0; j < 8; j++) acc[i][j] = 0.f;

    const float* Ap = A + (size_t)(bm * 128 + arow) * K + acol;
    const float* Bp = Bmat + (size_t)brow * ldb + wcol0 + bcol;

    for (int k0 = 0; k0 < K; k0 += 8) {
        float4 a4 = *(const float4*)(Ap + k0);
        As[acol + 0][arow] = a4.x;
        As[acol + 1][arow] = a4.y;
        As[acol + 2][arow] = a4.z;
        As[acol + 3][arow] = a4.w;
        float4 b4 = *(const float4*)(Bp + (size_t)k0 * ldb);
        *(float4*)&Bs[brow][bcol] = b4;
        __syncthreads();
#pragma unroll
        for (int kk = 0; kk < 8; kk++) {
            float ra[8], rb[8];
#pragma unroll
            for (int t = 0; t < 8; t++) { ra[t] = As[kk][tr + t]; rb[t] = Bs[kk][tc + t]; }
#pragma unroll
            for (int ii = 0; ii < 8; ii++)
#pragma unroll
                for (int jj = 0; jj < 8; jj++)
                    acc[ii][jj] = fmaf(ra[ii], rb[jj], acc[ii][jj]);
        }
        __syncthreads();
    }

#pragma unroll
    for (int ii = 0; ii < 8; ii++) {
        size_t row = (size_t)(bm * 128 + tr + ii);
        float* crow = C + row * OD_ + ccol0 + tc;
#pragma unroll
        for (int jj = 0; jj < 8; jj++)
            crow[jj] = acc[ii][jj] + bias[wcol0 + tc + jj];
    }
}

// ---------------------------------------------------------------------------
// Column sums of v per batch: g_vsum[b, od] = sum_s g_v[b, s, od]
// Grid (4, B_), 256 threads.
// ---------------------------------------------------------------------------
__global__ void vsum_kernel()
{
    int b  = blockIdx.y;
    int od = blockIdx.x * 256 + threadIdx.x;
    const float* vp = g_v + (size_t)b * S_ * OD_ + od;
    float s = 0.f;
    for (int j = 0; j < S_; j++) s += vp[(size_t)j * OD_];
    g_vsum[b * OD_ + od] = s;
}

// ---------------------------------------------------------------------------
// Banded attention: one warp per (b, h, i) row. 256 threads = 8 rows/block.
// Writes the FULL w row (zeros outside band: exact, since exp(-1e9-max)
// underflows to 0.0f) and updated_m = m_feats + r.
// Special case: entire band masked -> softmax over all-equal(-1e9) logits
// = uniform 1/S over ALL columns; r = vsum / S.
// ---------------------------------------------------------------------------
__global__ __launch_bounds__(256) void attn_kernel(
    const float* __restrict__ feats,
    const int*   __restrict__ mask,
    float* __restrict__ out_m,
    float* __restrict__ out_w)
{
    const int warp = threadIdx.x >> 5;
    const int lane = threadIdx.x & 31;
    const int row  = blockIdx.x * 8 + warp;       // ((b*H + h)*S + i)
    const int i  = row & (S_ - 1);
    const int bh = row >> 10;
    const int h  = bh & (H_ - 1);
    const int b  = bh >> 4;

    const float* kp = g_k + ((size_t)(b * S_ + i)) * OD_ + h * HD_;
    const int d0 = lane * 2;
    const float k0 = kp[d0], k1 = kp[d0 + 1];

    const int jbase = i - KHALF;
    float my_sc = -1e9f;   // lane jj owns score for j = jbase + jj (jj < 15)

#pragma unroll
    for (int jj = 0; jj < 15; jj++) {
        int j = jbase + jj;
        bool inr = (j >= 0) && (j < S_);
        int jc = inr ? j : 0;
        const float* qp = g_q + ((size_t)(b * S_ + jc)) * OD_ + h * HD_;
        float p = k0 * qp[d0] + k1 * qp[d0 + 1];
#pragma unroll
        for (int off = 16; off; off >>= 1) p += __shfl_xor_sync(0xffffffffu, p, off);
        bool valid = inr && (mask[b * S_ + jc] != 0);
        if (lane == jj) my_sc = valid ? p * 0.125f : -1e9f;
    }

    // softmax over the band (lanes 15..31 hold -1e9)
    float m = my_sc;
#pragma unroll
    for (int off = 16; off; off >>= 1) m = fmaxf(m, __shfl_xor_sync(0xffffffffu, m, off));
    const bool uniform = (m == -1e9f);

    float e = (lane < 15 && !uniform) ? expf(my_sc - m) : 0.f;
    float den = e;
#pragma unroll
    for (int off = 16; off; off >>= 1) den += __shfl_xor_sync(0xffffffffu, den, off);
    const float myw = uniform ? 0.f : e / den;

    // ---- write full w row (1024 floats) as float4, coalesced ----
    const float invS = 1.0f / (float)S_;
    float* wrow = out_w + (size_t)row * S_;
#pragma unroll
    for (int t = 0; t < 8; t++) {
        int c0 = (t * 32 + lane) * 4;   // base column for this lane's float4
        float4 val;
        float* vv = (float*)&val;
#pragma unroll
        for (int u = 0; u < 4; u++) {
            int jj = c0 + u - jbase;
            unsigned sl = (unsigned)min(max(jj, 0), 31);
            float bandv = __shfl_sync(0xffffffffu, myw, sl);
            vv[u] = uniform ? invS : ((jj >= 0 && jj < 15) ? bandv : 0.f);
        }
        *(float4*)(wrow + c0) = val;
    }

    // ---- r = sum_j w_ij * v_j ----
    float r0, r1;
    if (uniform) {
        r0 = g_vsum[b * OD_ + h * HD_ + d0]     * invS;
        r1 = g_vsum[b * OD_ + h * HD_ + d0 + 1] * invS;
    } else {
        r0 = 0.f; r1 = 0.f;
#pragma unroll
        for (int jj = 0; jj < 15; jj++) {
            float wv = __shfl_sync(0xffffffffu, myw, jj);
            int j = jbase + jj;
            if (j >= 0 && j < S_ && wv != 0.f) {
                const float* vp = g_v + ((size_t)(b * S_ + j)) * OD_ + h * HD_;
                r0 = fmaf(wv, vp[d0],     r0);
                r1 = fmaf(wv, vp[d0 + 1], r1);
            }
        }
    }

    size_t oidx = ((size_t)(b * S_ + i)) * OD_ + h * HD_ + d0;
    out_m[oidx]     = feats[oidx]     + r0;
    out_m[oidx + 1] = feats[oidx + 1] + r1;
}

// ---------------------------------------------------------------------------
extern "C" void kernel_launch(void* const* d_in, const int* in_sizes, int n_in,
                              void* d_out, int out_size)
{
    const float* feats = (const float*)d_in[0];
    const int*   mask  = (const int*)  d_in[1];
    const float* Wc    = (const float*)d_in[2];
    const float* bc    = (const float*)d_in[3];
    const float* Wv    = (const float*)d_in[4];
    const float* bv    = (const float*)d_in[5];

    float* out   = (float*)d_out;
    float* out_m = out;                                    // [B,S,ODIM]
    float* out_w = out + (size_t)B_ * S_ * OD_;            // [B,H,S,S]

    gemm_qkv<<<dim3(24, 64), 256>>>(feats, Wc, bc, Wv, bv);
    vsum_kernel<<<dim3(4, B_), 256>>>();
    attn_kernel<<<(B_ * H_ * S_) / 8, 256>>>(feats, mask, out_m, out_w);
}

// round 4
// speedup vs baseline: 2.0007x; 2.0007x over previous
#include <cuda_runtime.h>
#include <cuda_bf16.h>
#include <math.h>
#include <stdint.h>

// Problem constants
#define B_   8
#define S_   1024
#define ID_  1024
#define OD_  1024
#define H_   16
#define HD_  64
#define M_   8192          // B*S rows
#define NT_  3072          // q(1024) | v(1024) | k(1024) fused N
#define KHALF 7

// ---------------- device scratch (no allocations allowed) -------------------
__device__ __align__(128) __nv_bfloat16 g_Ah[(size_t)M_ * ID_];
__device__ __align__(128) __nv_bfloat16 g_Al[(size_t)M_ * ID_];
__device__ __align__(128) __nv_bfloat16 g_Wth[(size_t)NT_ * ID_];   // W^T hi [n][k]
__device__ __align__(128) __nv_bfloat16 g_Wtl[(size_t)NT_ * ID_];   // W^T lo [n][k]
__device__ float g_bias[NT_];
__device__ __align__(128) float g_qvk[(size_t)M_ * NT_];            // [row][ q | v | k ]
__device__ float g_vsum[B_ * OD_];

// ---------------- PTX helpers (sm_80/90 portable only) ----------------------
__device__ __forceinline__ uint32_t smem_u32(const void* p) {
    uint32_t a;
    asm("{ .reg .u64 t; cvta.to.shared.u64 t, %1; cvt.u32.u64 %0, t; }" : "=r"(a) : "l"(p));
    return a;
}
__device__ __forceinline__ void cp_async16(uint32_t dst, const void* src) {
    asm volatile("cp.async.cg.shared.global [%0], [%1], 16;" :: "r"(dst), "l"(src));
}
#define CP_COMMIT() asm volatile("cp.async.commit_group;" ::: "memory")

__device__ __forceinline__ void ldsm4(uint32_t* r, uint32_t addr) {
    asm volatile("ldmatrix.sync.aligned.m8n8.x4.shared.b16 {%0,%1,%2,%3}, [%4];"
        : "=r"(r[0]), "=r"(r[1]), "=r"(r[2]), "=r"(r[3]) : "r"(addr));
}
__device__ __forceinline__ void mma_bf16(float* c, const uint32_t* a, const uint32_t* b) {
    asm volatile("mma.sync.aligned.m16n8k16.row.col.f32.bf16.bf16.f32 "
        "{%0,%1,%2,%3}, {%4,%5,%6,%7}, {%8,%9}, {%0,%1,%2,%3};"
        : "+f"(c[0]), "+f"(c[1]), "+f"(c[2]), "+f"(c[3])
        : "r"(a[0]), "r"(a[1]), "r"(a[2]), "r"(a[3]), "r"(b[0]), "r"(b[1]));
}

// ---------------------------------------------------------------------------
// Conversion: A (m_feats) -> bf16 hi/lo, row-major [8192,1024]
// ---------------------------------------------------------------------------
__global__ __launch_bounds__(256) void conv_A(const float* __restrict__ A)
{
    size_t idx = (size_t)blockIdx.x * 256 + threadIdx.x;   // float4 index
    float4 a = ((const float4*)A)[idx];
    float v[4] = {a.x, a.y, a.z, a.w};
    __nv_bfloat16 h[4], l[4];
#pragma unroll
    for (int j = 0; j < 4; j++) {
        h[j] = __float2bfloat16(v[j]);
        l[j] = __float2bfloat16(v[j] - __bfloat162float(h[j]));
    }
    ((uint2*)g_Ah)[idx] = *(uint2*)h;
    ((uint2*)g_Al)[idx] = *(uint2*)l;
}

// ---------------------------------------------------------------------------
// Conversion: W^T hi/lo. Wt[n][k] = (n<2048 ? Wc[k][n] : Wv[k][n-2048])
// ---------------------------------------------------------------------------
__global__ void conv_W(const float* __restrict__ Wc, const float* __restrict__ Wv)
{
    __shared__ float ts[32][33];
    int n0 = blockIdx.x * 32, k0 = blockIdx.y * 32;
    int tx = threadIdx.x, ty = threadIdx.y;
#pragma unroll
    for (int j = 0; j < 32; j += 8) {
        int k = k0 + ty + j, n = n0 + tx;
        float val = (n < 2 * OD_) ? Wc[(size_t)k * (2 * OD_) + n]
                                  : Wv[(size_t)k * OD_ + (n - 2 * OD_)];
        ts[ty + j][tx] = val;
    }
    __syncthreads();
#pragma unroll
    for (int j = 0; j < 32; j += 8) {
        float val = ts[tx][ty + j];
        __nv_bfloat16 h = __float2bfloat16(val);
        __nv_bfloat16 l = __float2bfloat16(val - __bfloat162float(h));
        size_t o = (size_t)(n0 + ty + j) * ID_ + (k0 + tx);
        g_Wth[o] = h;
        g_Wtl[o] = l;
    }
}

__global__ void bias_k(const float* __restrict__ bc, const float* __restrict__ bv)
{
    int i = blockIdx.x * 256 + threadIdx.x;
    if (i < NT_) g_bias[i] = (i < 2 * OD_) ? bc[i] : bv[i - 2 * OD_];
}

// ---------------------------------------------------------------------------
// HMMA GEMM: C[8192,3072] = A @ W + bias via bf16x3 split.
// CTA 128x128, BK=32, 3-stage cp.async, 8 warps (2m x 4n), warp tile 64x32.
// SMEM per stage: Ah|Al|Bh|Bl, each 128 rows x 64B (swizzled) = 32KB.
// ---------------------------------------------------------------------------
#define AH_OFF 0
#define AL_OFF 8192
#define BH_OFF 16384
#define BL_OFF 24576
#define STAGE_SZ 32768
#define GEMM_SMEM (3 * STAGE_SZ)
#define NCHUNK 32

// swizzled offset within a 128x64B tile: row*64 + ((chunk ^ (row&3))*16)
__device__ __forceinline__ uint32_t tile_off(int row, int chunk) {
    return (uint32_t)(row * 64 + ((chunk ^ (row & 3)) << 4));
}

__device__ __forceinline__ void load_chunk(uint32_t stage, int m0, int n0, int c, int tid)
{
    const int k0 = c * 32;
    const char* srcs[4] = {
        (const char*)g_Ah  + ((size_t)m0 * ID_ + k0) * 2,
        (const char*)g_Al  + ((size_t)m0 * ID_ + k0) * 2,
        (const char*)g_Wth + ((size_t)n0 * ID_ + k0) * 2,
        (const char*)g_Wtl + ((size_t)n0 * ID_ + k0) * 2
    };
    const uint32_t offs[4] = {AH_OFF, AL_OFF, BH_OFF, BL_OFF};
#pragma unroll
    for (int mi = 0; mi < 4; mi++) {
        const char* s = srcs[mi];
        uint32_t dbase = stage + offs[mi];
#pragma unroll
        for (int it = 0; it < 2; it++) {
            int e = tid + it * 256;          // 0..511
            int row = e >> 2, chunk = e & 3;
            cp_async16(dbase + tile_off(row, chunk), s + (size_t)row * 2048 + chunk * 16);
        }
    }
}

extern "C" __global__ void __launch_bounds__(256, 1) gemm_tc()
{
    extern __shared__ char smem[];
    const uint32_t sb = smem_u32(smem);
    const int tid = threadIdx.x, wid = tid >> 5, lane = tid & 31;
    const int n0 = blockIdx.x * 128, m0 = blockIdx.y * 128;
    const int wm = wid >> 2, wn = wid & 3;          // 2 x 4 warp grid

    float acc[4][4][4];
#pragma unroll
    for (int a = 0; a < 4; a++)
#pragma unroll
        for (int b = 0; b < 4; b++)
#pragma unroll
            for (int d = 0; d < 4; d++) acc[a][b][d] = 0.f;

    // lane-invariant pieces of ldmatrix addresses
    const int a_row = wm * 64 + (lane & 15);        // + mt*16
    const int a_sel = lane >> 4;                    // 0/1 -> k-halves
    const int b_n   = wn * 32 + ((lane >> 4) & 1) * 8 + (lane & 7);  // + nt2*16
    const int b_sel = (lane >> 3) & 1;

    // prologue: stages 0,1
    load_chunk(sb + 0 * STAGE_SZ, m0, n0, 0, tid); CP_COMMIT();
    load_chunk(sb + 1 * STAGE_SZ, m0, n0, 1, tid); CP_COMMIT();

    for (int c = 0; c < NCHUNK; c++) {
        if (c + 2 < NCHUNK)
            load_chunk(sb + ((c + 2) % 3) * STAGE_SZ, m0, n0, c + 2, tid);
        CP_COMMIT();                                  // always: keeps group math uniform
        asm volatile("cp.async.wait_group 2;" ::: "memory");
        __syncthreads();

        const uint32_t stage = sb + (c % 3) * STAGE_SZ;
#pragma unroll
        for (int ks = 0; ks < 2; ks++) {
            uint32_t ah[4][4], al[4][4], bh[2][4], bl[2][4];
#pragma unroll
            for (int mt = 0; mt < 4; mt++) {
                int row = a_row + mt * 16, ch = ks * 2 + a_sel;
                ldsm4(ah[mt], stage + AH_OFF + tile_off(row, ch));
                ldsm4(al[mt], stage + AL_OFF + tile_off(row, ch));
            }
#pragma unroll
            for (int nt = 0; nt < 2; nt++) {
                int n = b_n + nt * 16, ch = ks * 2 + b_sel;
                ldsm4(bh[nt], stage + BH_OFF + tile_off(n, ch));
                ldsm4(bl[nt], stage + BL_OFF + tile_off(n, ch));
            }
#pragma unroll
            for (int mt = 0; mt < 4; mt++) {
#pragma unroll
                for (int ng = 0; ng < 4; ng++) {
                    uint32_t bfh[2] = { bh[ng >> 1][(ng & 1) * 2], bh[ng >> 1][(ng & 1) * 2 + 1] };
                    uint32_t bfl[2] = { bl[ng >> 1][(ng & 1) * 2], bl[ng >> 1][(ng & 1) * 2 + 1] };
                    mma_bf16(acc[mt][ng], ah[mt], bfh);
                    mma_bf16(acc[mt][ng], ah[mt], bfl);
                    mma_bf16(acc[mt][ng], al[mt], bfh);
                }
            }
        }
        __syncthreads();   // all warps done with stage c%3 before it is overwritten
    }

    // epilogue: write acc + bias to g_qvk
    const int g  = lane >> 2;            // group row
    const int tc = (lane & 3) * 2;       // col pair base
    const int m0w = m0 + wm * 64, n0w = n0 + wn * 32;
#pragma unroll
    for (int mt = 0; mt < 4; mt++) {
#pragma unroll
        for (int r2 = 0; r2 < 2; r2++) {
            int row = m0w + mt * 16 + g + r2 * 8;
            float* orow = g_qvk + (size_t)row * NT_ + n0w;
#pragma unroll
            for (int ng = 0; ng < 4; ng++) {
                int col = ng * 8 + tc;
                float2 o;
                o.x = acc[mt][ng][r2 * 2 + 0] + g_bias[n0w + col];
                o.y = acc[mt][ng][r2 * 2 + 1] + g_bias[n0w + col + 1];
                *(float2*)(orow + col) = o;
            }
        }
    }
}

// ---------------------------------------------------------------------------
// vsum over seq of v (needed for fully-masked rows): v = qvk col 1024+od
// ---------------------------------------------------------------------------
__global__ void vsum_kernel()
{
    int b  = blockIdx.y;
    int od = blockIdx.x * 256 + threadIdx.x;
    const float* vp = g_qvk + (size_t)b * S_ * NT_ + OD_ + od;
    float s = 0.f;
    for (int j = 0; j < S_; j++) s += vp[(size_t)j * NT_];
    g_vsum[b * OD_ + od] = s;
}

// ---------------------------------------------------------------------------
// Banded attention. One warp per (b,h,i). Writes full w row + updated_m.
// ---------------------------------------------------------------------------
__global__ __launch_bounds__(256) void attn_kernel(
    const float* __restrict__ feats,
    const int*   __restrict__ mask,
    float* __restrict__ out_m,
    float* __restrict__ out_w)
{
    const int warp = threadIdx.x >> 5;
    const int lane = threadIdx.x & 31;
    const int row  = blockIdx.x * 8 + warp;       // ((b*H + h)*S + i)
    const int i  = row & (S_ - 1);
    const int bh = row >> 10;
    const int h  = bh & (H_ - 1);
    const int b  = bh >> 4;

    const float* kp = g_qvk + ((size_t)(b * S_ + i)) * NT_ + 2 * OD_ + h * HD_;
    const int d0 = lane * 2;
    const float k0 = kp[d0], k1 = kp[d0 + 1];

    const int jbase = i - KHALF;
    float my_sc = -1e9f;

#pragma unroll
    for (int jj = 0; jj < 15; jj++) {
        int j = jbase + jj;
        bool inr = (j >= 0) && (j < S_);
        int jc = inr ? j : 0;
        const float* qp = g_qvk + ((size_t)(b * S_ + jc)) * NT_ + h * HD_;
        float p = k0 * qp[d0] + k1 * qp[d0 + 1];
#pragma unroll
        for (int off = 16; off; off >>= 1) p += __shfl_xor_sync(0xffffffffu, p, off);
        bool valid = inr && (mask[b * S_ + jc] != 0);
        if (lane == jj) my_sc = valid ? p * 0.125f : -1e9f;
    }

    float m = my_sc;
#pragma unroll
    for (int off = 16; off; off >>= 1) m = fmaxf(m, __shfl_xor_sync(0xffffffffu, m, off));
    const bool uniform = (m == -1e9f);

    float e = (lane < 15 && !uniform) ? expf(my_sc - m) : 0.f;
    float den = e;
#pragma unroll
    for (int off = 16; off; off >>= 1) den += __shfl_xor_sync(0xffffffffu, den, off);
    const float myw = uniform ? 0.f : e / den;

    const float invS = 1.0f / (float)S_;
    float* wrow = out_w + (size_t)row * S_;
#pragma unroll
    for (int t = 0; t < 8; t++) {
        int c0 = (t * 32 + lane) * 4;
        float4 val;
        float* vv = (float*)&val;
#pragma unroll
        for (int u = 0; u < 4; u++) {
            int jj = c0 + u - jbase;
            unsigned sl = (unsigned)min(max(jj, 0), 31);
            float bandv = __shfl_sync(0xffffffffu, myw, sl);
            vv[u] = uniform ? invS : ((jj >= 0 && jj < 15) ? bandv : 0.f);
        }
        *(float4*)(wrow + c0) = val;
    }

    float r0, r1;
    if (uniform) {
        r0 = g_vsum[b * OD_ + h * HD_ + d0]     * invS;
        r1 = g_vsum[b * OD_ + h * HD_ + d0 + 1] * invS;
    } else {
        r0 = 0.f; r1 = 0.f;
#pragma unroll
        for (int jj = 0; jj < 15; jj++) {
            float wv = __shfl_sync(0xffffffffu, myw, jj);
            int j = jbase + jj;
            if (j >= 0 && j < S_ && wv != 0.f) {
                const float* vp = g_qvk + ((size_t)(b * S_ + j)) * NT_ + OD_ + h * HD_;
                r0 = fmaf(wv, vp[d0],     r0);
                r1 = fmaf(wv, vp[d0 + 1], r1);
            }
        }
    }

    size_t oidx = ((size_t)(b * S_ + i)) * OD_ + h * HD_ + d0;
    out_m[oidx]     = feats[oidx]     + r0;
    out_m[oidx + 1] = feats[oidx + 1] + r1;
}

// ---------------------------------------------------------------------------
extern "C" void kernel_launch(void* const* d_in, const int* in_sizes, int n_in,
                              void* d_out, int out_size)
{
    const float* feats = (const float*)d_in[0];
    const int*   mask  = (const int*)  d_in[1];
    const float* Wc    = (const float*)d_in[2];
    const float* bc    = (const float*)d_in[3];
    const float* Wv    = (const float*)d_in[4];
    const float* bv    = (const float*)d_in[5];

    float* out   = (float*)d_out;
    float* out_m = out;
    float* out_w = out + (size_t)B_ * S_ * OD_;

    static int smem_set = 0;
    if (!smem_set) {
        cudaFuncSetAttribute(gemm_tc, cudaFuncAttributeMaxDynamicSharedMemorySize, GEMM_SMEM);
        smem_set = 1;
    }

    conv_A<<<(M_ * ID_ / 4) / 256, 256>>>(feats);
    conv_W<<<dim3(NT_ / 32, ID_ / 32), dim3(32, 8)>>>(Wc, Wv);
    bias_k<<<(NT_ + 255) / 256, 256>>>(bc, bv);
    gemm_tc<<<dim3(NT_ / 128, M_ / 128), 256, GEMM_SMEM>>>();
    vsum_kernel<<<dim3(4, B_), 256>>>();
    attn_kernel<<<(B_ * H_ * S_) / 8, 256>>>(feats, mask, out_m, out_w);
}

// round 5
// speedup vs baseline: 2.2836x; 1.1414x over previous
#include <cuda_runtime.h>
#include <cuda_bf16.h>
#include <math.h>
#include <stdint.h>

// Problem constants
#define B_   8
#define S_   1024
#define ID_  1024
#define OD_  1024
#define H_   16
#define HD_  64
#define M_   8192          // B*S rows
#define NT_  3072          // q(1024) | v(1024) | k(1024) fused N
#define KHALF 7

// ---------------- device scratch (no allocations allowed) -------------------
__device__ __align__(128) __nv_bfloat16 g_Ah[(size_t)M_ * ID_];
__device__ __align__(128) __nv_bfloat16 g_Al[(size_t)M_ * ID_];
__device__ __align__(128) __nv_bfloat16 g_Wth[(size_t)NT_ * ID_];   // W^T hi [n][k]
__device__ __align__(128) __nv_bfloat16 g_Wtl[(size_t)NT_ * ID_];   // W^T lo [n][k]
__device__ float g_bias[NT_];
__device__ __align__(128) float g_qvk[(size_t)M_ * NT_];            // [row][ q | v | k ]
__device__ float g_vsum[B_ * OD_];

// ---------------- PTX helpers (sm_80/90 portable only) ----------------------
__device__ __forceinline__ uint32_t smem_u32(const void* p) {
    uint32_t a;
    asm("{ .reg .u64 t; cvta.to.shared.u64 t, %1; cvt.u32.u64 %0, t; }" : "=r"(a) : "l"(p));
    return a;
}
__device__ __forceinline__ void cp_async16(uint32_t dst, const void* src) {
    asm volatile("cp.async.cg.shared.global [%0], [%1], 16;" :: "r"(dst), "l"(src));
}
#define CP_COMMIT() asm volatile("cp.async.commit_group;" ::: "memory")

__device__ __forceinline__ void ldsm4(uint32_t* r, uint32_t addr) {
    asm volatile("ldmatrix.sync.aligned.m8n8.x4.shared.b16 {%0,%1,%2,%3}, [%4];"
        : "=r"(r[0]), "=r"(r[1]), "=r"(r[2]), "=r"(r[3]) : "r"(addr));
}
__device__ __forceinline__ void mma_bf16(float* c, const uint32_t* a, const uint32_t* b) {
    asm volatile("mma.sync.aligned.m16n8k16.row.col.f32.bf16.bf16.f32 "
        "{%0,%1,%2,%3}, {%4,%5,%6,%7}, {%8,%9}, {%0,%1,%2,%3};"
        : "+f"(c[0]), "+f"(c[1]), "+f"(c[2]), "+f"(c[3])
        : "r"(a[0]), "r"(a[1]), "r"(a[2]), "r"(a[3]), "r"(b[0]), "r"(b[1]));
}

// ---------------------------------------------------------------------------
// Conversion: A (m_feats) -> bf16 hi/lo, row-major [8192,1024]
// ---------------------------------------------------------------------------
__global__ __launch_bounds__(256) void conv_A(const float* __restrict__ A)
{
    size_t idx = (size_t)blockIdx.x * 256 + threadIdx.x;   // float4 index
    float4 a = ((const float4*)A)[idx];
    float v[4] = {a.x, a.y, a.z, a.w};
    __nv_bfloat16 h[4], l[4];
#pragma unroll
    for (int j = 0; j < 4; j++) {
        h[j] = __float2bfloat16(v[j]);
        l[j] = __float2bfloat16(v[j] - __bfloat162float(h[j]));
    }
    ((uint2*)g_Ah)[idx] = *(uint2*)h;
    ((uint2*)g_Al)[idx] = *(uint2*)l;
}

// ---------------------------------------------------------------------------
// Conversion: W^T hi/lo. Wt[n][k] = (n<2048 ? Wc[k][n] : Wv[k][n-2048])
// ---------------------------------------------------------------------------
__global__ void conv_W(const float* __restrict__ Wc, const float* __restrict__ Wv)
{
    __shared__ float ts[32][33];
    int n0 = blockIdx.x * 32, k0 = blockIdx.y * 32;
    int tx = threadIdx.x, ty = threadIdx.y;
#pragma unroll
    for (int j = 0; j < 32; j += 8) {
        int k = k0 + ty + j, n = n0 + tx;
        float val = (n < 2 * OD_) ? Wc[(size_t)k * (2 * OD_) + n]
                                  : Wv[(size_t)k * OD_ + (n - 2 * OD_)];
        ts[ty + j][tx] = val;
    }
    __syncthreads();
#pragma unroll
    for (int j = 0; j < 32; j += 8) {
        float val = ts[tx][ty + j];
        __nv_bfloat16 h = __float2bfloat16(val);
        __nv_bfloat16 l = __float2bfloat16(val - __bfloat162float(h));
        size_t o = (size_t)(n0 + ty + j) * ID_ + (k0 + tx);
        g_Wth[o] = h;
        g_Wtl[o] = l;
    }
}

__global__ void bias_k(const float* __restrict__ bc, const float* __restrict__ bv)
{
    int i = blockIdx.x * 256 + threadIdx.x;
    if (i < NT_) g_bias[i] = (i < 2 * OD_) ? bc[i] : bv[i - 2 * OD_];
}

// ---------------------------------------------------------------------------
// HMMA GEMM: C[8192,3072] = A @ W + bias via bf16x3 split.
// CTA 128x128, BK=32, 2-stage cp.async double buffer, 8 warps (2m x 4n),
// warp tile 64x32. 64KB smem -> 2 CTAs/SM. Conflict-free swizzle.
// ---------------------------------------------------------------------------
#define AH_OFF 0
#define AL_OFF 8192
#define BH_OFF 16384
#define BL_OFF 24576
#define STAGE_SZ 32768
#define GEMM_SMEM (2 * STAGE_SZ)
#define NCHUNK 32

// swizzled offset within a 128-row x 64B tile; conflict-free for ldmatrix:
// 16B slice index = chunk ^ ((row>>1)&3)
__device__ __forceinline__ uint32_t tile_off(int row, int chunk) {
    return (uint32_t)(row * 64 + (((chunk ^ ((row >> 1) & 3)) & 3) << 4));
}

__device__ __forceinline__ void load_chunk(uint32_t stage, int m0, int n0, int c, int tid)
{
    const int k0 = c * 32;
    const char* srcs[4] = {
        (const char*)g_Ah  + ((size_t)m0 * ID_ + k0) * 2,
        (const char*)g_Al  + ((size_t)m0 * ID_ + k0) * 2,
        (const char*)g_Wth + ((size_t)n0 * ID_ + k0) * 2,
        (const char*)g_Wtl + ((size_t)n0 * ID_ + k0) * 2
    };
    const uint32_t offs[4] = {AH_OFF, AL_OFF, BH_OFF, BL_OFF};
#pragma unroll
    for (int mi = 0; mi < 4; mi++) {
        const char* s = srcs[mi];
        uint32_t dbase = stage + offs[mi];
#pragma unroll
        for (int it = 0; it < 2; it++) {
            int e = tid + it * 256;          // 0..511
            int row = e >> 2, chunk = e & 3;
            cp_async16(dbase + tile_off(row, chunk), s + (size_t)row * 2048 + chunk * 16);
        }
    }
}

extern "C" __global__ void __launch_bounds__(256, 2) gemm_tc()
{
    extern __shared__ char smem[];
    const uint32_t sb = smem_u32(smem);
    const int tid = threadIdx.x, wid = tid >> 5, lane = tid & 31;
    const int n0 = blockIdx.x * 128, m0 = blockIdx.y * 128;
    const int wm = wid >> 2, wn = wid & 3;          // 2 x 4 warp grid

    float acc[4][4][4];
#pragma unroll
    for (int a = 0; a < 4; a++)
#pragma unroll
        for (int b = 0; b < 4; b++)
#pragma unroll
            for (int d = 0; d < 4; d++) acc[a][b][d] = 0.f;

    // lane-invariant pieces of ldmatrix addresses
    const int a_row = wm * 64 + (lane & 15);        // + mt*16
    const int a_sel = lane >> 4;                    // 0/1 -> k-halves
    const int b_n   = wn * 32 + ((lane >> 4) & 1) * 8 + (lane & 7);  // + nt2*16
    const int b_sel = (lane >> 3) & 1;

    // prologue: chunks 0,1 into buffers 0,1
    load_chunk(sb + 0 * STAGE_SZ, m0, n0, 0, tid); CP_COMMIT();
    load_chunk(sb + 1 * STAGE_SZ, m0, n0, 1, tid); CP_COMMIT();

    for (int c = 0; c < NCHUNK; c++) {
        if (c < NCHUNK - 1) asm volatile("cp.async.wait_group 1;" ::: "memory");
        else                asm volatile("cp.async.wait_group 0;" ::: "memory");
        __syncthreads();

        const uint32_t stage = sb + (c & 1) * STAGE_SZ;
#pragma unroll
        for (int ks = 0; ks < 2; ks++) {
            uint32_t ah[4][4], al[4][4], bh[2][4], bl[2][4];
#pragma unroll
            for (int mt = 0; mt < 4; mt++) {
                int row = a_row + mt * 16, ch = ks * 2 + a_sel;
                ldsm4(ah[mt], stage + AH_OFF + tile_off(row, ch));
                ldsm4(al[mt], stage + AL_OFF + tile_off(row, ch));
            }
#pragma unroll
            for (int nt = 0; nt < 2; nt++) {
                int n = b_n + nt * 16, ch = ks * 2 + b_sel;
                ldsm4(bh[nt], stage + BH_OFF + tile_off(n, ch));
                ldsm4(bl[nt], stage + BL_OFF + tile_off(n, ch));
            }
#pragma unroll
            for (int mt = 0; mt < 4; mt++) {
#pragma unroll
                for (int ng = 0; ng < 4; ng++) {
                    uint32_t bfh[2] = { bh[ng >> 1][(ng & 1) * 2], bh[ng >> 1][(ng & 1) * 2 + 1] };
                    uint32_t bfl[2] = { bl[ng >> 1][(ng & 1) * 2], bl[ng >> 1][(ng & 1) * 2 + 1] };
                    mma_bf16(acc[mt][ng], ah[mt], bfh);
                    mma_bf16(acc[mt][ng], ah[mt], bfl);
                    mma_bf16(acc[mt][ng], al[mt], bfh);
                }
            }
        }
        __syncthreads();   // all warps done reading this buffer

        if (c + 2 < NCHUNK) {
            load_chunk(stage, m0, n0, c + 2, tid);   // refill the buffer just freed
            CP_COMMIT();
        }
    }

    // epilogue: write acc + bias to g_qvk
    const int g  = lane >> 2;            // group row
    const int tc = (lane & 3) * 2;       // col pair base
    const int m0w = m0 + wm * 64, n0w = n0 + wn * 32;
#pragma unroll
    for (int mt = 0; mt < 4; mt++) {
#pragma unroll
        for (int r2 = 0; r2 < 2; r2++) {
            int row = m0w + mt * 16 + g + r2 * 8;
            float* orow = g_qvk + (size_t)row * NT_ + n0w;
#pragma unroll
            for (int ng = 0; ng < 4; ng++) {
                int col = ng * 8 + tc;
                float2 o;
                o.x = acc[mt][ng][r2 * 2 + 0] + g_bias[n0w + col];
                o.y = acc[mt][ng][r2 * 2 + 1] + g_bias[n0w + col + 1];
                *(float2*)(orow + col) = o;
            }
        }
    }
}

// ---------------------------------------------------------------------------
// vsum over seq of v (needed for fully-masked rows): v = qvk col 1024+od
// ---------------------------------------------------------------------------
__global__ void vsum_kernel()
{
    int b  = blockIdx.y;
    int od = blockIdx.x * 256 + threadIdx.x;
    const float* vp = g_qvk + (size_t)b * S_ * NT_ + OD_ + od;
    float s = 0.f;
    for (int j = 0; j < S_; j++) s += vp[(size_t)j * NT_];
    g_vsum[b * OD_ + od] = s;
}

// ---------------------------------------------------------------------------
// Banded attention. One warp per (b,h,i). Writes full w row + updated_m.
// ---------------------------------------------------------------------------
__global__ __launch_bounds__(256) void attn_kernel(
    const float* __restrict__ feats,
    const int*   __restrict__ mask,
    float* __restrict__ out_m,
    float* __restrict__ out_w)
{
    const int warp = threadIdx.x >> 5;
    const int lane = threadIdx.x & 31;
    const int row  = blockIdx.x * 8 + warp;       // ((b*H + h)*S + i)
    const int i  = row & (S_ - 1);
    const int bh = row >> 10;
    const int h  = bh & (H_ - 1);
    const int b  = bh >> 4;

    const float* kp = g_qvk + ((size_t)(b * S_ + i)) * NT_ + 2 * OD_ + h * HD_;
    const int d0 = lane * 2;
    const float k0 = kp[d0], k1 = kp[d0 + 1];

    const int jbase = i - KHALF;
    float my_sc = -1e9f;

#pragma unroll
    for (int jj = 0; jj < 15; jj++) {
        int j = jbase + jj;
        bool inr = (j >= 0) && (j < S_);
        int jc = inr ? j : 0;
        const float* qp = g_qvk + ((size_t)(b * S_ + jc)) * NT_ + h * HD_;
        float p = k0 * qp[d0] + k1 * qp[d0 + 1];
#pragma unroll
        for (int off = 16; off; off >>= 1) p += __shfl_xor_sync(0xffffffffu, p, off);
        bool valid = inr && (mask[b * S_ + jc] != 0);
        if (lane == jj) my_sc = valid ? p * 0.125f : -1e9f;
    }

    float m = my_sc;
#pragma unroll
    for (int off = 16; off; off >>= 1) m = fmaxf(m, __shfl_xor_sync(0xffffffffu, m, off));
    const bool uniform = (m == -1e9f);

    float e = (lane < 15 && !uniform) ? expf(my_sc - m) : 0.f;
    float den = e;
#pragma unroll
    for (int off = 16; off; off >>= 1) den += __shfl_xor_sync(0xffffffffu, den, off);
    const float myw = uniform ? 0.f : e / den;

    const float invS = 1.0f / (float)S_;
    float* wrow = out_w + (size_t)row * S_;
#pragma unroll
    for (int t = 0; t < 8; t++) {
        int c0 = (t * 32 + lane) * 4;
        float4 val;
        float* vv = (float*)&val;
#pragma unroll
        for (int u = 0; u < 4; u++) {
            int jj = c0 + u - jbase;
            unsigned sl = (unsigned)min(max(jj, 0), 31);
            float bandv = __shfl_sync(0xffffffffu, myw, sl);
            vv[u] = uniform ? invS : ((jj >= 0 && jj < 15) ? bandv : 0.f);
        }
        *(float4*)(wrow + c0) = val;
    }

    float r0, r1;
    if (uniform) {
        r0 = g_vsum[b * OD_ + h * HD_ + d0]     * invS;
        r1 = g_vsum[b * OD_ + h * HD_ + d0 + 1] * invS;
    } else {
        r0 = 0.f; r1 = 0.f;
#pragma unroll
        for (int jj = 0; jj < 15; jj++) {
            float wv = __shfl_sync(0xffffffffu, myw, jj);
            int j = jbase + jj;
            if (j >= 0 && j < S_ && wv != 0.f) {
                const float* vp = g_qvk + ((size_t)(b * S_ + j)) * NT_ + OD_ + h * HD_;
                r0 = fmaf(wv, vp[d0],     r0);
                r1 = fmaf(wv, vp[d0 + 1], r1);
            }
        }
    }

    size_t oidx = ((size_t)(b * S_ + i)) * OD_ + h * HD_ + d0;
    out_m[oidx]     = feats[oidx]     + r0;
    out_m[oidx + 1] = feats[oidx + 1] + r1;
}

// ---------------------------------------------------------------------------
extern "C" void kernel_launch(void* const* d_in, const int* in_sizes, int n_in,
                              void* d_out, int out_size)
{
    const float* feats = (const float*)d_in[0];
    const int*   mask  = (const int*)  d_in[1];
    const float* Wc    = (const float*)d_in[2];
    const float* bc    = (const float*)d_in[3];
    const float* Wv    = (const float*)d_in[4];
    const float* bv    = (const float*)d_in[5];

    float* out   = (float*)d_out;
    float* out_m = out;
    float* out_w = out + (size_t)B_ * S_ * OD_;

    static int smem_set = 0;
    if (!smem_set) {
        cudaFuncSetAttribute(gemm_tc, cudaFuncAttributeMaxDynamicSharedMemorySize, GEMM_SMEM);
        smem_set = 1;
    }

    conv_A<<<(M_ * ID_ / 4) / 256, 256>>>(feats);
    conv_W<<<dim3(NT_ / 32, ID_ / 32), dim3(32, 8)>>>(Wc, Wv);
    bias_k<<<(NT_ + 255) / 256, 256>>>(bc, bv);
    gemm_tc<<<dim3(NT_ / 128, M_ / 128), 256, GEMM_SMEM>>>();
    vsum_kernel<<<dim3(4, B_), 256>>>();
    attn_kernel<<<(B_ * H_ * S_) / 8, 256>>>(feats, mask, out_m, out_w);
}

// round 6
// speedup vs baseline: 2.6189x; 1.1469x over previous
#include <cuda_runtime.h>
#include <cuda_bf16.h>
#include <math.h>
#include <stdint.h>

// Problem constants
#define B_   8
#define S_   1024
#define ID_  1024
#define OD_  1024
#define H_   16
#define HD_  64
#define M_   8192          // B*S rows
#define NT_  3072          // q(1024) | v(1024) | k(1024) fused N
#define KHALF 7

// ---------------- device scratch (no allocations allowed) -------------------
__device__ __align__(128) __nv_bfloat16 g_Ah[(size_t)M_ * ID_];
__device__ __align__(128) __nv_bfloat16 g_Al[(size_t)M_ * ID_];
__device__ __align__(128) __nv_bfloat16 g_Wth[(size_t)NT_ * ID_];   // W^T hi [n][k]
__device__ __align__(128) __nv_bfloat16 g_Wtl[(size_t)NT_ * ID_];   // W^T lo [n][k]
__device__ float g_bias[NT_];
__device__ __align__(128) float g_qvk[(size_t)M_ * NT_];            // [row][ q | v | k ]
__device__ float g_vsum[B_ * OD_];

// ---------------- PTX helpers (sm_80/90 portable only) ----------------------
__device__ __forceinline__ uint32_t smem_u32(const void* p) {
    uint32_t a;
    asm("{ .reg .u64 t; cvta.to.shared.u64 t, %1; cvt.u32.u64 %0, t; }" : "=r"(a) : "l"(p));
    return a;
}
__device__ __forceinline__ void cp_async16(uint32_t dst, const void* src) {
    asm volatile("cp.async.cg.shared.global [%0], [%1], 16;" :: "r"(dst), "l"(src));
}
#define CP_COMMIT() asm volatile("cp.async.commit_group;" ::: "memory")

__device__ __forceinline__ void ldsm4(uint32_t* r, uint32_t addr) {
    asm volatile("ldmatrix.sync.aligned.m8n8.x4.shared.b16 {%0,%1,%2,%3}, [%4];"
        : "=r"(r[0]), "=r"(r[1]), "=r"(r[2]), "=r"(r[3]) : "r"(addr));
}
__device__ __forceinline__ void mma_bf16(float* c, const uint32_t* a, const uint32_t* b) {
    asm volatile("mma.sync.aligned.m16n8k16.row.col.f32.bf16.bf16.f32 "
        "{%0,%1,%2,%3}, {%4,%5,%6,%7}, {%8,%9}, {%0,%1,%2,%3};"
        : "+f"(c[0]), "+f"(c[1]), "+f"(c[2]), "+f"(c[3])
        : "r"(a[0]), "r"(a[1]), "r"(a[2]), "r"(a[3]), "r"(b[0]), "r"(b[1]));
}

// ---------------------------------------------------------------------------
// Conversion: A (m_feats) -> bf16 hi/lo, row-major [8192,1024]
// ---------------------------------------------------------------------------
__global__ __launch_bounds__(256) void conv_A(const float* __restrict__ A)
{
    size_t idx = (size_t)blockIdx.x * 256 + threadIdx.x;   // float4 index
    float4 a = ((const float4*)A)[idx];
    float v[4] = {a.x, a.y, a.z, a.w};
    __nv_bfloat16 h[4], l[4];
#pragma unroll
    for (int j = 0; j < 4; j++) {
        h[j] = __float2bfloat16(v[j]);
        l[j] = __float2bfloat16(v[j] - __bfloat162float(h[j]));
    }
    ((uint2*)g_Ah)[idx] = *(uint2*)h;
    ((uint2*)g_Al)[idx] = *(uint2*)l;
}

// ---------------------------------------------------------------------------
// Conversion: W^T hi/lo. Wt[n][k] = (n<2048 ? Wc[k][n] : Wv[k][n-2048])
// ---------------------------------------------------------------------------
__global__ void conv_W(const float* __restrict__ Wc, const float* __restrict__ Wv)
{
    __shared__ float ts[32][33];
    int n0 = blockIdx.x * 32, k0 = blockIdx.y * 32;
    int tx = threadIdx.x, ty = threadIdx.y;
#pragma unroll
    for (int j = 0; j < 32; j += 8) {
        int k = k0 + ty + j, n = n0 + tx;
        float val = (n < 2 * OD_) ? Wc[(size_t)k * (2 * OD_) + n]
                                  : Wv[(size_t)k * OD_ + (n - 2 * OD_)];
        ts[ty + j][tx] = val;
    }
    __syncthreads();
#pragma unroll
    for (int j = 0; j < 32; j += 8) {
        float val = ts[tx][ty + j];
        __nv_bfloat16 h = __float2bfloat16(val);
        __nv_bfloat16 l = __float2bfloat16(val - __bfloat162float(h));
        size_t o = (size_t)(n0 + ty + j) * ID_ + (k0 + tx);
        g_Wth[o] = h;
        g_Wtl[o] = l;
    }
}

__global__ void bias_k(const float* __restrict__ bc, const float* __restrict__ bv)
{
    int i = blockIdx.x * 256 + threadIdx.x;
    if (i < NT_) g_bias[i] = (i < 2 * OD_) ? bc[i] : bv[i - 2 * OD_];
}

// ---------------------------------------------------------------------------
// HMMA GEMM: C[8192,3072] = A @ W + bias via bf16x3 split.
// CTA 128x128, BK=32, 3-stage cp.async, ONE sync per chunk, 8 warps (2m x 4n),
// warp tile 64x32. 96KB smem -> 2 CTAs/SM.
// ---------------------------------------------------------------------------
#define AH_OFF 0
#define AL_OFF 8192
#define BH_OFF 16384
#define BL_OFF 24576
#define STAGE_SZ 32768
#define GEMM_SMEM (3 * STAGE_SZ)
#define NCHUNK 32

// swizzled offset within a 128-row x 64B tile; conflict-free for ldmatrix:
// 16B slice index = chunk ^ ((row>>1)&3)
__device__ __forceinline__ uint32_t tile_off(int row, int chunk) {
    return (uint32_t)(row * 64 + (((chunk ^ ((row >> 1) & 3)) & 3) << 4));
}

__device__ __forceinline__ void load_chunk(uint32_t stage, int m0, int n0, int c, int tid)
{
    const int k0 = c * 32;
    const char* srcs[4] = {
        (const char*)g_Ah  + ((size_t)m0 * ID_ + k0) * 2,
        (const char*)g_Al  + ((size_t)m0 * ID_ + k0) * 2,
        (const char*)g_Wth + ((size_t)n0 * ID_ + k0) * 2,
        (const char*)g_Wtl + ((size_t)n0 * ID_ + k0) * 2
    };
    const uint32_t offs[4] = {AH_OFF, AL_OFF, BH_OFF, BL_OFF};
#pragma unroll
    for (int mi = 0; mi < 4; mi++) {
        const char* s = srcs[mi];
        uint32_t dbase = stage + offs[mi];
#pragma unroll
        for (int it = 0; it < 2; it++) {
            int e = tid + it * 256;          // 0..511
            int row = e >> 2, chunk = e & 3;
            cp_async16(dbase + tile_off(row, chunk), s + (size_t)row * 2048 + chunk * 16);
        }
    }
}

extern "C" __global__ void __launch_bounds__(256, 2) gemm_tc()
{
    extern __shared__ char smem[];
    const uint32_t sb = smem_u32(smem);
    const int tid = threadIdx.x, wid = tid >> 5, lane = tid & 31;
    const int n0 = blockIdx.x * 128, m0 = blockIdx.y * 128;
    const int wm = wid >> 2, wn = wid & 3;          // 2 x 4 warp grid

    float acc[4][4][4];
#pragma unroll
    for (int a = 0; a < 4; a++)
#pragma unroll
        for (int b = 0; b < 4; b++)
#pragma unroll
            for (int d = 0; d < 4; d++) acc[a][b][d] = 0.f;

    // lane-invariant pieces of ldmatrix addresses
    const int a_row = wm * 64 + (lane & 15);        // + mt*16
    const int a_sel = lane >> 4;                    // 0/1 -> k-halves
    const int b_n   = wn * 32 + ((lane >> 4) & 1) * 8 + (lane & 7);  // + nt2*16
    const int b_sel = (lane >> 3) & 1;

    // prologue: chunks 0,1 into buffers 0,1
    load_chunk(sb + 0 * STAGE_SZ, m0, n0, 0, tid); CP_COMMIT();
    load_chunk(sb + 1 * STAGE_SZ, m0, n0, 1, tid); CP_COMMIT();

    uint32_t buf = 0;   // buffer index of chunk c (c % 3)

    for (int c = 0; c < NCHUNK; c++) {
        if (c < NCHUNK - 1) asm volatile("cp.async.wait_group 1;" ::: "memory");
        else                asm volatile("cp.async.wait_group 0;" ::: "memory");
        // single barrier: chunk c resident AND all warps done computing c-1
        __syncthreads();

        // refill the buffer freed by compute(c-1) BEFORE computing c
        if (c + 2 < NCHUNK) {
            uint32_t nbuf = buf + 2; if (nbuf >= 3) nbuf -= 3;
            load_chunk(sb + nbuf * STAGE_SZ, m0, n0, c + 2, tid);
            CP_COMMIT();
        }

        const uint32_t stage = sb + buf * STAGE_SZ;
#pragma unroll
        for (int ks = 0; ks < 2; ks++) {
            uint32_t ah[4][4], al[4][4], bh[2][4], bl[2][4];
#pragma unroll
            for (int mt = 0; mt < 4; mt++) {
                int row = a_row + mt * 16, ch = ks * 2 + a_sel;
                ldsm4(ah[mt], stage + AH_OFF + tile_off(row, ch));
                ldsm4(al[mt], stage + AL_OFF + tile_off(row, ch));
            }
#pragma unroll
            for (int nt = 0; nt < 2; nt++) {
                int n = b_n + nt * 16, ch = ks * 2 + b_sel;
                ldsm4(bh[nt], stage + BH_OFF + tile_off(n, ch));
                ldsm4(bl[nt], stage + BL_OFF + tile_off(n, ch));
            }
#pragma unroll
            for (int mt = 0; mt < 4; mt++) {
#pragma unroll
                for (int ng = 0; ng < 4; ng++) {
                    uint32_t bfh[2] = { bh[ng >> 1][(ng & 1) * 2], bh[ng >> 1][(ng & 1) * 2 + 1] };
                    uint32_t bfl[2] = { bl[ng >> 1][(ng & 1) * 2], bl[ng >> 1][(ng & 1) * 2 + 1] };
                    mma_bf16(acc[mt][ng], ah[mt], bfh);
                    mma_bf16(acc[mt][ng], ah[mt], bfl);
                    mma_bf16(acc[mt][ng], al[mt], bfh);
                }
            }
        }

        buf++; if (buf >= 3) buf -= 3;
    }

    // epilogue: write acc + bias to g_qvk
    const int g  = lane >> 2;            // group row
    const int tc = (lane & 3) * 2;       // col pair base
    const int m0w = m0 + wm * 64, n0w = n0 + wn * 32;
#pragma unroll
    for (int mt = 0; mt < 4; mt++) {
#pragma unroll
        for (int r2 = 0; r2 < 2; r2++) {
            int row = m0w + mt * 16 + g + r2 * 8;
            float* orow = g_qvk + (size_t)row * NT_ + n0w;
#pragma unroll
            for (int ng = 0; ng < 4; ng++) {
                int col = ng * 8 + tc;
                float2 o;
                o.x = acc[mt][ng][r2 * 2 + 0] + g_bias[n0w + col];
                o.y = acc[mt][ng][r2 * 2 + 1] + g_bias[n0w + col + 1];
                *(float2*)(orow + col) = o;
            }
        }
    }
}

// ---------------------------------------------------------------------------
// vsum over seq of v (needed for fully-masked rows): v = qvk col 1024+od
// ---------------------------------------------------------------------------
__global__ void vsum_kernel()
{
    int b  = blockIdx.y;
    int od = blockIdx.x * 256 + threadIdx.x;
    const float* vp = g_qvk + (size_t)b * S_ * NT_ + OD_ + od;
    float s = 0.f;
    for (int j = 0; j < S_; j++) s += vp[(size_t)j * NT_];
    g_vsum[b * OD_ + od] = s;
}

// ---------------------------------------------------------------------------
// Banded attention. One warp per (b,h,i). Writes full w row + updated_m.
// ---------------------------------------------------------------------------
__global__ __launch_bounds__(256) void attn_kernel(
    const float* __restrict__ feats,
    const int*   __restrict__ mask,
    float* __restrict__ out_m,
    float* __restrict__ out_w)
{
    const int warp = threadIdx.x >> 5;
    const int lane = threadIdx.x & 31;
    const int row  = blockIdx.x * 8 + warp;       // ((b*H + h)*S + i)
    const int i  = row & (S_ - 1);
    const int bh = row >> 10;
    const int h  = bh & (H_ - 1);
    const int b  = bh >> 4;

    const float* kp = g_qvk + ((size_t)(b * S_ + i)) * NT_ + 2 * OD_ + h * HD_;
    const int d0 = lane * 2;
    const float k0 = kp[d0], k1 = kp[d0 + 1];

    const int jbase = i - KHALF;
    float my_sc = -1e9f;

#pragma unroll
    for (int jj = 0; jj < 15; jj++) {
        int j = jbase + jj;
        bool inr = (j >= 0) && (j < S_);
        int jc = inr ? j : 0;
        const float* qp = g_qvk + ((size_t)(b * S_ + jc)) * NT_ + h * HD_;
        float p = k0 * qp[d0] + k1 * qp[d0 + 1];
#pragma unroll
        for (int off = 16; off; off >>= 1) p += __shfl_xor_sync(0xffffffffu, p, off);
        bool valid = inr && (mask[b * S_ + jc] != 0);
        if (lane == jj) my_sc = valid ? p * 0.125f : -1e9f;
    }

    float m = my_sc;
#pragma unroll
    for (int off = 16; off; off >>= 1) m = fmaxf(m, __shfl_xor_sync(0xffffffffu, m, off));
    const bool uniform = (m == -1e9f);

    float e = (lane < 15 && !uniform) ? expf(my_sc - m) : 0.f;
    float den = e;
#pragma unroll
    for (int off = 16; off; off >>= 1) den += __shfl_xor_sync(0xffffffffu, den, off);
    const float myw = uniform ? 0.f : e / den;

    const float invS = 1.0f / (float)S_;
    float* wrow = out_w + (size_t)row * S_;
#pragma unroll
    for (int t = 0; t < 8; t++) {
        int c0 = (t * 32 + lane) * 4;
        float4 val;
        float* vv = (float*)&val;
#pragma unroll
        for (int u = 0; u < 4; u++) {
            int jj = c0 + u - jbase;
            unsigned sl = (unsigned)min(max(jj, 0), 31);
            float bandv = __shfl_sync(0xffffffffu, myw, sl);
            vv[u] = uniform ? invS : ((jj >= 0 && jj < 15) ? bandv : 0.f);
        }
        *(float4*)(wrow + c0) = val;
    }

    float r0, r1;
    if (uniform) {
        r0 = g_vsum[b * OD_ + h * HD_ + d0]     * invS;
        r1 = g_vsum[b * OD_ + h * HD_ + d0 + 1] * invS;
    } else {
        r0 = 0.f; r1 = 0.f;
#pragma unroll
        for (int jj = 0; jj < 15; jj++) {
            float wv = __shfl_sync(0xffffffffu, myw, jj);
            int j = jbase + jj;
            if (j >= 0 && j < S_ && wv != 0.f) {
                const float* vp = g_qvk + ((size_t)(b * S_ + j)) * NT_ + OD_ + h * HD_;
                r0 = fmaf(wv, vp[d0],     r0);
                r1 = fmaf(wv, vp[d0 + 1], r1);
            }
        }
    }

    size_t oidx = ((size_t)(b * S_ + i)) * OD_ + h * HD_ + d0;
    out_m[oidx]     = feats[oidx]     + r0;
    out_m[oidx + 1] = feats[oidx + 1] + r1;
}

// ---------------------------------------------------------------------------
extern "C" void kernel_launch(void* const* d_in, const int* in_sizes, int n_in,
                              void* d_out, int out_size)
{
    const float* feats = (const float*)d_in[0];
    const int*   mask  = (const int*)  d_in[1];
    const float* Wc    = (const float*)d_in[2];
    const float* bc    = (const float*)d_in[3];
    const float* Wv    = (const float*)d_in[4];
    const float* bv    = (const float*)d_in[5];

    float* out   = (float*)d_out;
    float* out_m = out;
    float* out_w = out + (size_t)B_ * S_ * OD_;

    static int smem_set = 0;
    if (!smem_set) {
        cudaFuncSetAttribute(gemm_tc, cudaFuncAttributeMaxDynamicSharedMemorySize, GEMM_SMEM);
        smem_set = 1;
    }

    conv_A<<<(M_ * ID_ / 4) / 256, 256>>>(feats);
    conv_W<<<dim3(NT_ / 32, ID_ / 32), dim3(32, 8)>>>(Wc, Wv);
    bias_k<<<(NT_ + 255) / 256, 256>>>(bc, bv);
    gemm_tc<<<dim3(NT_ / 128, M_ / 128), 256, GEMM_SMEM>>>();
    vsum_kernel<<<dim3(4, B_), 256>>>();
    attn_kernel<<<(B_ * H_ * S_) / 8, 256>>>(feats, mask, out_m, out_w);
}

// round 7
// speedup vs baseline: 2.6534x; 1.0132x over previous
#include <cuda_runtime.h>
#include <cuda_bf16.h>
#include <math.h>
#include <stdint.h>

// Problem constants
#define B_   8
#define S_   1024
#define ID_  1024
#define OD_  1024
#define H_   16
#define HD_  64
#define M_   8192          // B*S rows
#define NT_  3072          // q(1024) | v(1024) | k(1024) fused N
#define KHALF 7

// ---------------- device scratch (no allocations allowed) -------------------
__device__ __align__(128) __nv_bfloat16 g_Ah[(size_t)M_ * ID_];
__device__ __align__(128) __nv_bfloat16 g_Al[(size_t)M_ * ID_];
__device__ __align__(128) __nv_bfloat16 g_Wth[(size_t)NT_ * ID_];   // W^T hi [n][k]
__device__ __align__(128) __nv_bfloat16 g_Wtl[(size_t)NT_ * ID_];   // W^T lo [n][k]
__device__ float g_bias[NT_];
__device__ __align__(128) float g_qvk[(size_t)M_ * NT_];            // [row][ q | v | k ]
__device__ float g_vsum[B_ * OD_];

// ---------------- PTX helpers (sm_80/90 portable only) ----------------------
__device__ __forceinline__ uint32_t smem_u32(const void* p) {
    uint32_t a;
    asm("{ .reg .u64 t; cvta.to.shared.u64 t, %1; cvt.u32.u64 %0, t; }" : "=r"(a) : "l"(p));
    return a;
}
__device__ __forceinline__ void cp_async16(uint32_t dst, const void* src) {
    asm volatile("cp.async.cg.shared.global [%0], [%1], 16;" :: "r"(dst), "l"(src));
}
#define CP_COMMIT() asm volatile("cp.async.commit_group;" ::: "memory")

__device__ __forceinline__ void ldsm4(uint32_t* r, uint32_t addr) {
    asm volatile("ldmatrix.sync.aligned.m8n8.x4.shared.b16 {%0,%1,%2,%3}, [%4];"
        : "=r"(r[0]), "=r"(r[1]), "=r"(r[2]), "=r"(r[3]) : "r"(addr));
}
__device__ __forceinline__ void mma_bf16(float* c, const uint32_t* a, const uint32_t* b) {
    asm volatile("mma.sync.aligned.m16n8k16.row.col.f32.bf16.bf16.f32 "
        "{%0,%1,%2,%3}, {%4,%5,%6,%7}, {%8,%9}, {%0,%1,%2,%3};"
        : "+f"(c[0]), "+f"(c[1]), "+f"(c[2]), "+f"(c[3])
        : "r"(a[0]), "r"(a[1]), "r"(a[2]), "r"(a[3]), "r"(b[0]), "r"(b[1]));
}

// ---------------------------------------------------------------------------
// Conversion: A (m_feats) -> bf16 hi/lo, row-major [8192,1024]
// ---------------------------------------------------------------------------
__global__ __launch_bounds__(256) void conv_A(const float* __restrict__ A)
{
    size_t idx = (size_t)blockIdx.x * 256 + threadIdx.x;   // float4 index
    float4 a = ((const float4*)A)[idx];
    float v[4] = {a.x, a.y, a.z, a.w};
    __nv_bfloat16 h[4], l[4];
#pragma unroll
    for (int j = 0; j < 4; j++) {
        h[j] = __float2bfloat16(v[j]);
        l[j] = __float2bfloat16(v[j] - __bfloat162float(h[j]));
    }
    ((uint2*)g_Ah)[idx] = *(uint2*)h;
    ((uint2*)g_Al)[idx] = *(uint2*)l;
}

// ---------------------------------------------------------------------------
// Conversion: W^T hi/lo. Wt[n][k] = (n<2048 ? Wc[k][n] : Wv[k][n-2048])
// ---------------------------------------------------------------------------
__global__ void conv_W(const float* __restrict__ Wc, const float* __restrict__ Wv)
{
    __shared__ float ts[32][33];
    int n0 = blockIdx.x * 32, k0 = blockIdx.y * 32;
    int tx = threadIdx.x, ty = threadIdx.y;
#pragma unroll
    for (int j = 0; j < 32; j += 8) {
        int k = k0 + ty + j, n = n0 + tx;
        float val = (n < 2 * OD_) ? Wc[(size_t)k * (2 * OD_) + n]
                                  : Wv[(size_t)k * OD_ + (n - 2 * OD_)];
        ts[ty + j][tx] = val;
    }
    __syncthreads();
#pragma unroll
    for (int j = 0; j < 32; j += 8) {
        float val = ts[tx][ty + j];
        __nv_bfloat16 h = __float2bfloat16(val);
        __nv_bfloat16 l = __float2bfloat16(val - __bfloat162float(h));
        size_t o = (size_t)(n0 + ty + j) * ID_ + (k0 + tx);
        g_Wth[o] = h;
        g_Wtl[o] = l;
    }
}

__global__ void bias_k(const float* __restrict__ bc, const float* __restrict__ bv)
{
    int i = blockIdx.x * 256 + threadIdx.x;
    if (i < NT_) g_bias[i] = (i < 2 * OD_) ? bc[i] : bv[i - 2 * OD_];
}

// ---------------------------------------------------------------------------
// HMMA GEMM: C[8192,3072] = A @ W + bias via bf16x3 split.
// CTA 128x128, BK=32, 3-stage cp.async, ONE sync per chunk.
// 4 warps (2m x 2n), warp tile 64x64 -> ldsm:mma = 32:192.
// 96KB smem -> 2 CTAs/SM.
// ---------------------------------------------------------------------------
#define AH_OFF 0
#define AL_OFF 8192
#define BH_OFF 16384
#define BL_OFF 24576
#define STAGE_SZ 32768
#define GEMM_SMEM (3 * STAGE_SZ)
#define NCHUNK 32

// swizzled offset within a 128-row x 64B tile; conflict-free for ldmatrix:
// 16B slice index = chunk ^ ((row>>1)&3)
__device__ __forceinline__ uint32_t tile_off(int row, int chunk) {
    return (uint32_t)(row * 64 + (((chunk ^ ((row >> 1) & 3)) & 3) << 4));
}

__device__ __forceinline__ void load_chunk(uint32_t stage, int m0, int n0, int c, int tid)
{
    const int k0 = c * 32;
    const char* srcs[4] = {
        (const char*)g_Ah  + ((size_t)m0 * ID_ + k0) * 2,
        (const char*)g_Al  + ((size_t)m0 * ID_ + k0) * 2,
        (const char*)g_Wth + ((size_t)n0 * ID_ + k0) * 2,
        (const char*)g_Wtl + ((size_t)n0 * ID_ + k0) * 2
    };
    const uint32_t offs[4] = {AH_OFF, AL_OFF, BH_OFF, BL_OFF};
#pragma unroll
    for (int mi = 0; mi < 4; mi++) {
        const char* s = srcs[mi];
        uint32_t dbase = stage + offs[mi];
#pragma unroll
        for (int it = 0; it < 4; it++) {
            int e = tid + it * 128;          // 0..511
            int row = e >> 2, chunk = e & 3;
            cp_async16(dbase + tile_off(row, chunk), s + (size_t)row * 2048 + chunk * 16);
        }
    }
}

extern "C" __global__ void __launch_bounds__(128, 2) gemm_tc()
{
    extern __shared__ char smem[];
    const uint32_t sb = smem_u32(smem);
    const int tid = threadIdx.x, wid = tid >> 5, lane = tid & 31;
    const int n0 = blockIdx.x * 128, m0 = blockIdx.y * 128;
    const int wm = wid >> 1, wn = wid & 1;          // 2 x 2 warp grid, tile 64x64

    float acc[4][8][4];
#pragma unroll
    for (int a = 0; a < 4; a++)
#pragma unroll
        for (int b = 0; b < 8; b++)
#pragma unroll
            for (int d = 0; d < 4; d++) acc[a][b][d] = 0.f;

    // lane-invariant pieces of ldmatrix addresses
    const int a_row = wm * 64 + (lane & 15);        // + mt*16
    const int a_sel = lane >> 4;                    // 0/1 -> k-halves
    const int b_n   = wn * 64 + ((lane >> 4) & 1) * 8 + (lane & 7);  // + nt*16
    const int b_sel = (lane >> 3) & 1;

    // prologue: chunks 0,1 into buffers 0,1
    load_chunk(sb + 0 * STAGE_SZ, m0, n0, 0, tid); CP_COMMIT();
    load_chunk(sb + 1 * STAGE_SZ, m0, n0, 1, tid); CP_COMMIT();

    uint32_t buf = 0;   // buffer index of chunk c (c % 3)

    for (int c = 0; c < NCHUNK; c++) {
        if (c < NCHUNK - 1) asm volatile("cp.async.wait_group 1;" ::: "memory");
        else                asm volatile("cp.async.wait_group 0;" ::: "memory");
        // single barrier: chunk c resident AND all warps done computing c-1
        __syncthreads();

        // refill the buffer freed by compute(c-1) BEFORE computing c
        if (c + 2 < NCHUNK) {
            uint32_t nbuf = buf + 2; if (nbuf >= 3) nbuf -= 3;
            load_chunk(sb + nbuf * STAGE_SZ, m0, n0, c + 2, tid);
            CP_COMMIT();
        }

        const uint32_t stage = sb + buf * STAGE_SZ;
#pragma unroll
        for (int ks = 0; ks < 2; ks++) {
            uint32_t ah[4][4], al[4][4], bh[4][4], bl[4][4];
#pragma unroll
            for (int mt = 0; mt < 4; mt++) {
                int row = a_row + mt * 16, ch = ks * 2 + a_sel;
                ldsm4(ah[mt], stage + AH_OFF + tile_off(row, ch));
                ldsm4(al[mt], stage + AL_OFF + tile_off(row, ch));
            }
#pragma unroll
            for (int nt = 0; nt < 4; nt++) {
                int n = b_n + nt * 16, ch = ks * 2 + b_sel;
                ldsm4(bh[nt], stage + BH_OFF + tile_off(n, ch));
                ldsm4(bl[nt], stage + BL_OFF + tile_off(n, ch));
            }
#pragma unroll
            for (int mt = 0; mt < 4; mt++) {
#pragma unroll
                for (int ng = 0; ng < 8; ng++) {
                    uint32_t bfh[2] = { bh[ng >> 1][(ng & 1) * 2], bh[ng >> 1][(ng & 1) * 2 + 1] };
                    uint32_t bfl[2] = { bl[ng >> 1][(ng & 1) * 2], bl[ng >> 1][(ng & 1) * 2 + 1] };
                    mma_bf16(acc[mt][ng], ah[mt], bfh);
                    mma_bf16(acc[mt][ng], ah[mt], bfl);
                    mma_bf16(acc[mt][ng], al[mt], bfh);
                }
            }
        }

        buf++; if (buf >= 3) buf -= 3;
    }

    // epilogue: write acc + bias to g_qvk
    const int g  = lane >> 2;            // group row
    const int tc = (lane & 3) * 2;       // col pair base
    const int m0w = m0 + wm * 64, n0w = n0 + wn * 64;
#pragma unroll
    for (int mt = 0; mt < 4; mt++) {
#pragma unroll
        for (int r2 = 0; r2 < 2; r2++) {
            int row = m0w + mt * 16 + g + r2 * 8;
            float* orow = g_qvk + (size_t)row * NT_ + n0w;
#pragma unroll
            for (int ng = 0; ng < 8; ng++) {
                int col = ng * 8 + tc;
                float2 o;
                o.x = acc[mt][ng][r2 * 2 + 0] + g_bias[n0w + col];
                o.y = acc[mt][ng][r2 * 2 + 1] + g_bias[n0w + col + 1];
                *(float2*)(orow + col) = o;
            }
        }
    }
}

// ---------------------------------------------------------------------------
// vsum over seq of v (needed for fully-masked rows): v = qvk col 1024+od
// ---------------------------------------------------------------------------
__global__ void vsum_kernel()
{
    int b  = blockIdx.y;
    int od = blockIdx.x * 256 + threadIdx.x;
    const float* vp = g_qvk + (size_t)b * S_ * NT_ + OD_ + od;
    float s = 0.f;
    for (int j = 0; j < S_; j++) s += vp[(size_t)j * NT_];
    g_vsum[b * OD_ + od] = s;
}

// ---------------------------------------------------------------------------
// Banded attention. One warp per (b,h,i). Writes full w row + updated_m.
// ---------------------------------------------------------------------------
__global__ __launch_bounds__(256) void attn_kernel(
    const float* __restrict__ feats,
    const int*   __restrict__ mask,
    float* __restrict__ out_m,
    float* __restrict__ out_w)
{
    const int warp = threadIdx.x >> 5;
    const int lane = threadIdx.x & 31;
    const int row  = blockIdx.x * 8 + warp;       // ((b*H + h)*S + i)
    const int i  = row & (S_ - 1);
    const int bh = row >> 10;
    const int h  = bh & (H_ - 1);
    const int b  = bh >> 4;

    const float* kp = g_qvk + ((size_t)(b * S_ + i)) * NT_ + 2 * OD_ + h * HD_;
    const int d0 = lane * 2;
    const float k0 = kp[d0], k1 = kp[d0 + 1];

    const int jbase = i - KHALF;
    float my_sc = -1e9f;

#pragma unroll
    for (int jj = 0; jj < 15; jj++) {
        int j = jbase + jj;
        bool inr = (j >= 0) && (j < S_);
        int jc = inr ? j : 0;
        const float* qp = g_qvk + ((size_t)(b * S_ + jc)) * NT_ + h * HD_;
        float p = k0 * qp[d0] + k1 * qp[d0 + 1];
#pragma unroll
        for (int off = 16; off; off >>= 1) p += __shfl_xor_sync(0xffffffffu, p, off);
        bool valid = inr && (mask[b * S_ + jc] != 0);
        if (lane == jj) my_sc = valid ? p * 0.125f : -1e9f;
    }

    float m = my_sc;
#pragma unroll
    for (int off = 16; off; off >>= 1) m = fmaxf(m, __shfl_xor_sync(0xffffffffu, m, off));
    const bool uniform = (m == -1e9f);

    float e = (lane < 15 && !uniform) ? expf(my_sc - m) : 0.f;
    float den = e;
#pragma unroll
    for (int off = 16; off; off >>= 1) den += __shfl_xor_sync(0xffffffffu, den, off);
    const float myw = uniform ? 0.f : e / den;

    const float invS = 1.0f / (float)S_;
    float* wrow = out_w + (size_t)row * S_;
#pragma unroll
    for (int t = 0; t < 8; t++) {
        int c0 = (t * 32 + lane) * 4;
        float4 val;
        float* vv = (float*)&val;
#pragma unroll
        for (int u = 0; u < 4; u++) {
            int jj = c0 + u - jbase;
            unsigned sl = (unsigned)min(max(jj, 0), 31);
            float bandv = __shfl_sync(0xffffffffu, myw, sl);
            vv[u] = uniform ? invS : ((jj >= 0 && jj < 15) ? bandv : 0.f);
        }
        *(float4*)(wrow + c0) = val;
    }

    float r0, r1;
    if (uniform) {
        r0 = g_vsum[b * OD_ + h * HD_ + d0]     * invS;
        r1 = g_vsum[b * OD_ + h * HD_ + d0 + 1] * invS;
    } else {
        r0 = 0.f; r1 = 0.f;
#pragma unroll
        for (int jj = 0; jj < 15; jj++) {
            float wv = __shfl_sync(0xffffffffu, myw, jj);
            int j = jbase + jj;
            if (j >= 0 && j < S_ && wv != 0.f) {
                const float* vp = g_qvk + ((size_t)(b * S_ + j)) * NT_ + OD_ + h * HD_;
                r0 = fmaf(wv, vp[d0],     r0);
                r1 = fmaf(wv, vp[d0 + 1], r1);
            }
        }
    }

    size_t oidx = ((size_t)(b * S_ + i)) * OD_ + h * HD_ + d0;
    out_m[oidx]     = feats[oidx]     + r0;
    out_m[oidx + 1] = feats[oidx + 1] + r1;
}

// ---------------------------------------------------------------------------
extern "C" void kernel_launch(void* const* d_in, const int* in_sizes, int n_in,
                              void* d_out, int out_size)
{
    const float* feats = (const float*)d_in[0];
    const int*   mask  = (const int*)  d_in[1];
    const float* Wc    = (const float*)d_in[2];
    const float* bc    = (const float*)d_in[3];
    const float* Wv    = (const float*)d_in[4];
    const float* bv    = (const float*)d_in[5];

    float* out   = (float*)d_out;
    float* out_m = out;
    float* out_w = out + (size_t)B_ * S_ * OD_;

    static int smem_set = 0;
    if (!smem_set) {
        cudaFuncSetAttribute(gemm_tc, cudaFuncAttributeMaxDynamicSharedMemorySize, GEMM_SMEM);
        smem_set = 1;
    }

    conv_A<<<(M_ * ID_ / 4) / 256, 256>>>(feats);
    conv_W<<<dim3(NT_ / 32, ID_ / 32), dim3(32, 8)>>>(Wc, Wv);
    bias_k<<<(NT_ + 255) / 256, 256>>>(bc, bv);
    gemm_tc<<<dim3(NT_ / 128, M_ / 128), 128, GEMM_SMEM>>>();
    vsum_kernel<<<dim3(4, B_), 256>>>();
    attn_kernel<<<(B_ * H_ * S_) / 8, 256>>>(feats, mask, out_m, out_w);
}

// round 9
// speedup vs baseline: 3.2722x; 1.2332x over previous
#include <cuda_runtime.h>
#include <cuda_fp16.h>
#include <math.h>
#include <stdint.h>

// Problem constants
#define B_   8
#define S_   1024
#define ID_  1024
#define OD_  1024
#define H_   16
#define HD_  64
#define M_   8192          // B*S rows
#define NT_  3072          // q(1024) | v(1024) | k(1024) fused N
#define KHALF 7

// ---------------- device scratch (no allocations allowed) -------------------
__device__ __align__(128) __half g_Ah[(size_t)M_ * ID_];
__device__ __align__(128) __half g_Al[(size_t)M_ * ID_];
__device__ __align__(128) __half g_Wt[(size_t)NT_ * ID_];    // W^T fp16 [n][k]
__device__ float g_bias[NT_];
__device__ __align__(128) float g_qvk[(size_t)M_ * NT_];     // [row][ q | v | k ]
__device__ float g_vsum[B_ * OD_];

// ---------------- PTX helpers (sm_80/90 portable only) ----------------------
__device__ __forceinline__ uint32_t smem_u32(const void* p) {
    uint32_t a;
    asm("{ .reg .u64 t; cvta.to.shared.u64 t, %1; cvt.u32.u64 %0, t; }" : "=r"(a) : "l"(p));
    return a;
}
__device__ __forceinline__ void cp_async16(uint32_t dst, const void* src) {
    asm volatile("cp.async.cg.shared.global [%0], [%1], 16;" :: "r"(dst), "l"(src));
}
#define CP_COMMIT() asm volatile("cp.async.commit_group;" ::: "memory")

__device__ __forceinline__ void ldsm4(uint32_t* r, uint32_t addr) {
    asm volatile("ldmatrix.sync.aligned.m8n8.x4.shared.b16 {%0,%1,%2,%3}, [%4];"
        : "=r"(r[0]), "=r"(r[1]), "=r"(r[2]), "=r"(r[3]) : "r"(addr));
}
__device__ __forceinline__ void mma_f16(float* c, const uint32_t* a, const uint32_t* b) {
    asm volatile("mma.sync.aligned.m16n8k16.row.col.f32.f16.f16.f32 "
        "{%0,%1,%2,%3}, {%4,%5,%6,%7}, {%8,%9}, {%0,%1,%2,%3};"
        : "+f"(c[0]), "+f"(c[1]), "+f"(c[2]), "+f"(c[3])
        : "r"(a[0]), "r"(a[1]), "r"(a[2]), "r"(a[3]), "r"(b[0]), "r"(b[1]));
}

// ---------------------------------------------------------------------------
// Conversion: A (m_feats) -> fp16 hi/lo, row-major [8192,1024]
// ---------------------------------------------------------------------------
__global__ __launch_bounds__(256) void conv_A(const float* __restrict__ A)
{
    size_t idx = (size_t)blockIdx.x * 256 + threadIdx.x;   // float4 index
    float4 a = ((const float4*)A)[idx];
    float v[4] = {a.x, a.y, a.z, a.w};
    __half h[4], l[4];
#pragma unroll
    for (int j = 0; j < 4; j++) {
        h[j] = __float2half_rn(v[j]);
        l[j] = __float2half_rn(v[j] - __half2float(h[j]));
    }
    ((uint2*)g_Ah)[idx] = *(uint2*)h;
    ((uint2*)g_Al)[idx] = *(uint2*)l;
}

// ---------------------------------------------------------------------------
// Conversion: W^T fp16. Wt[n][k] = (n<2048 ? Wc[k][n] : Wv[k][n-2048])
// ---------------------------------------------------------------------------
__global__ void conv_W(const float* __restrict__ Wc, const float* __restrict__ Wv)
{
    __shared__ float ts[32][33];
    int n0 = blockIdx.x * 32, k0 = blockIdx.y * 32;
    int tx = threadIdx.x, ty = threadIdx.y;
#pragma unroll
    for (int j = 0; j < 32; j += 8) {
        int k = k0 + ty + j, n = n0 + tx;
        float val = (n < 2 * OD_) ? Wc[(size_t)k * (2 * OD_) + n]
                                  : Wv[(size_t)k * OD_ + (n - 2 * OD_)];
        ts[ty + j][tx] = val;
    }
    __syncthreads();
#pragma unroll
    for (int j = 0; j < 32; j += 8) {
        float val = ts[tx][ty + j];
        size_t o = (size_t)(n0 + ty + j) * ID_ + (k0 + tx);
        g_Wt[o] = __float2half_rn(val);
    }
}

__global__ void bias_k(const float* __restrict__ bc, const float* __restrict__ bv)
{
    int i = blockIdx.x * 256 + threadIdx.x;
    if (i < NT_) g_bias[i] = (i < 2 * OD_) ? bc[i] : bv[i - 2 * OD_];
}

// ---------------------------------------------------------------------------
// HMMA GEMM: C[8192,3072] = A @ W + bias via fp16x2 split (A hi/lo, W single).
// CTA 128x128, BK=32, 4-stage cp.async, ONE sync per chunk.
// 4 warps (2m x 2n), warp tile 64x64. 96KB smem -> 2 CTAs/SM.
// ---------------------------------------------------------------------------
#define AH_OFF 0
#define AL_OFF 8192
#define BF_OFF 16384
#define STAGE_SZ 24576
#define NSTAGE 4
#define GEMM_SMEM (NSTAGE * STAGE_SZ)
#define NCHUNK 32

// swizzled offset within a 128-row x 64B tile; conflict-free for ldmatrix:
// 16B slice index = chunk ^ ((row>>1)&3)
__device__ __forceinline__ uint32_t tile_off(int row, int chunk) {
    return (uint32_t)(row * 64 + (((chunk ^ ((row >> 1) & 3)) & 3) << 4));
}

__device__ __forceinline__ void load_chunk(uint32_t stage, int m0, int n0, int c, int tid)
{
    const int k0 = c * 32;
    const char* srcs[3] = {
        (const char*)g_Ah + ((size_t)m0 * ID_ + k0) * 2,
        (const char*)g_Al + ((size_t)m0 * ID_ + k0) * 2,
        (const char*)g_Wt + ((size_t)n0 * ID_ + k0) * 2
    };
    const uint32_t offs[3] = {AH_OFF, AL_OFF, BF_OFF};
#pragma unroll
    for (int mi = 0; mi < 3; mi++) {
        const char* s = srcs[mi];
        uint32_t dbase = stage + offs[mi];
#pragma unroll
        for (int it = 0; it < 4; it++) {
            int e = tid + it * 128;          // 0..511
            int row = e >> 2, chunk = e & 3;
            cp_async16(dbase + tile_off(row, chunk), s + (size_t)row * 2048 + chunk * 16);
        }
    }
}

extern "C" __global__ void __launch_bounds__(128, 2) gemm_tc()
{
    extern __shared__ char smem[];
    const uint32_t sb = smem_u32(smem);
    const int tid = threadIdx.x, wid = tid >> 5, lane = tid & 31;
    const int n0 = blockIdx.x * 128, m0 = blockIdx.y * 128;
    const int wm = wid >> 1, wn = wid & 1;          // 2 x 2 warp grid, tile 64x64

    float acc[4][8][4];
#pragma unroll
    for (int a = 0; a < 4; a++)
#pragma unroll
        for (int b = 0; b < 8; b++)
#pragma unroll
            for (int d = 0; d < 4; d++) acc[a][b][d] = 0.f;

    // lane-invariant pieces of ldmatrix addresses
    const int a_row = wm * 64 + (lane & 15);        // + mt*16
    const int a_sel = lane >> 4;                    // 0/1 -> k-halves
    const int b_n   = wn * 64 + ((lane >> 4) & 1) * 8 + (lane & 7);  // + nt*16
    const int b_sel = (lane >> 3) & 1;

    // prologue: chunks 0,1,2 into buffers 0,1,2
    load_chunk(sb + 0 * STAGE_SZ, m0, n0, 0, tid); CP_COMMIT();
    load_chunk(sb + 1 * STAGE_SZ, m0, n0, 1, tid); CP_COMMIT();
    load_chunk(sb + 2 * STAGE_SZ, m0, n0, 2, tid); CP_COMMIT();

    uint32_t buf = 0;   // buffer index of chunk c (c % NSTAGE)

    for (int c = 0; c < NCHUNK; c++) {
        const int rem = NCHUNK - 1 - c;
        if (rem >= 2)      asm volatile("cp.async.wait_group 2;" ::: "memory");
        else if (rem == 1) asm volatile("cp.async.wait_group 1;" ::: "memory");
        else               asm volatile("cp.async.wait_group 0;" ::: "memory");
        // single barrier: chunk c resident AND all warps done computing c-1
        __syncthreads();

        // refill the buffer freed by compute(c-1) BEFORE computing c
        if (c + 3 < NCHUNK) {
            uint32_t nbuf = buf + 3; if (nbuf >= NSTAGE) nbuf -= NSTAGE;
            load_chunk(sb + nbuf * STAGE_SZ, m0, n0, c + 3, tid);
            CP_COMMIT();
        }

        const uint32_t stage = sb + buf * STAGE_SZ;
#pragma unroll
        for (int ks = 0; ks < 2; ks++) {
            uint32_t ah[4][4], al[4][4], bf[4][4];
#pragma unroll
            for (int mt = 0; mt < 4; mt++) {
                int row = a_row + mt * 16, ch = ks * 2 + a_sel;
                ldsm4(ah[mt], stage + AH_OFF + tile_off(row, ch));
                ldsm4(al[mt], stage + AL_OFF + tile_off(row, ch));
            }
#pragma unroll
            for (int nt = 0; nt < 4; nt++) {
                int n = b_n + nt * 16, ch = ks * 2 + b_sel;
                ldsm4(bf[nt], stage + BF_OFF + tile_off(n, ch));
            }
#pragma unroll
            for (int mt = 0; mt < 4; mt++) {
#pragma unroll
                for (int ng = 0; ng < 8; ng++) {
                    uint32_t b2[2] = { bf[ng >> 1][(ng & 1) * 2], bf[ng >> 1][(ng & 1) * 2 + 1] };
                    mma_f16(acc[mt][ng], ah[mt], b2);
                    mma_f16(acc[mt][ng], al[mt], b2);
                }
            }
        }

        buf++; if (buf >= NSTAGE) buf -= NSTAGE;
    }

    // epilogue: write acc + bias to g_qvk
    const int g  = lane >> 2;            // group row
    const int tc = (lane & 3) * 2;       // col pair base
    const int m0w = m0 + wm * 64, n0w = n0 + wn * 64;
#pragma unroll
    for (int mt = 0; mt < 4; mt++) {
#pragma unroll
        for (int r2 = 0; r2 < 2; r2++) {
            int row = m0w + mt * 16 + g + r2 * 8;
            float* orow = g_qvk + (size_t)row * NT_ + n0w;
#pragma unroll
            for (int ng = 0; ng < 8; ng++) {
                int col = ng * 8 + tc;
                float2 o;
                o.x = acc[mt][ng][r2 * 2 + 0] + g_bias[n0w + col];
                o.y = acc[mt][ng][r2 * 2 + 1] + g_bias[n0w + col + 1];
                *(float2*)(orow + col) = o;
            }
        }
    }
}

// ---------------------------------------------------------------------------
// vsum over seq of v (needed for fully-masked rows): v = qvk col 1024+od
// ---------------------------------------------------------------------------
__global__ void vsum_kernel()
{
    int b  = blockIdx.y;
    int od = blockIdx.x * 256 + threadIdx.x;
    const float* vp = g_qvk + (size_t)b * S_ * NT_ + OD_ + od;
    float s = 0.f;
    for (int j = 0; j < S_; j++) s += vp[(size_t)j * NT_];
    g_vsum[b * OD_ + od] = s;
}

// ---------------------------------------------------------------------------
// Banded attention. One warp per (b,h,i). Writes full w row + updated_m.
// Out-of-band 128-col segments take the fast pure-zero path.
// ---------------------------------------------------------------------------
__global__ __launch_bounds__(256) void attn_kernel(
    const float* __restrict__ feats,
    const int*   __restrict__ mask,
    float* __restrict__ out_m,
    float* __restrict__ out_w)
{
    const int warp = threadIdx.x >> 5;
    const int lane = threadIdx.x & 31;
    const int row  = blockIdx.x * 8 + warp;       // ((b*H + h)*S + i)
    const int i  = row & (S_ - 1);
    const int bh = row >> 10;
    const int h  = bh & (H_ - 1);
    const int b  = bh >> 4;

    const float* kp = g_qvk + ((size_t)(b * S_ + i)) * NT_ + 2 * OD_ + h * HD_;
    const int d0 = lane * 2;
    const float k0 = kp[d0], k1 = kp[d0 + 1];

    const int jbase = i - KHALF;
    float my_sc = -1e9f;

#pragma unroll
    for (int jj = 0; jj < 15; jj++) {
        int j = jbase + jj;
        bool inr = (j >= 0) && (j < S_);
        int jc = inr ? j : 0;
        const float* qp = g_qvk + ((size_t)(b * S_ + jc)) * NT_ + h * HD_;
        float p = k0 * qp[d0] + k1 * qp[d0 + 1];
#pragma unroll
        for (int off = 16; off; off >>= 1) p += __shfl_xor_sync(0xffffffffu, p, off);
        bool valid = inr && (mask[b * S_ + jc] != 0);
        if (lane == jj) my_sc = valid ? p * 0.125f : -1e9f;
    }

    float m = my_sc;
#pragma unroll
    for (int off = 16; off; off >>= 1) m = fmaxf(m, __shfl_xor_sync(0xffffffffu, m, off));
    const bool uniform = (m == -1e9f);

    float e = (lane < 15 && !uniform) ? expf(my_sc - m) : 0.f;
    float den = e;
#pragma unroll
    for (int off = 16; off; off >>= 1) den += __shfl_xor_sync(0xffffffffu, den, off);
    const float myw = uniform ? 0.f : e / den;

    const float invS = 1.0f / (float)S_;
    float* wrow = out_w + (size_t)row * S_;
    // segments (128 cols each) that intersect the band
    const int t_lo = max(jbase, 0) >> 7;
    const int t_hi = min(jbase + 14, S_ - 1) >> 7;
#pragma unroll
    for (int t = 0; t < 8; t++) {
        int c0 = t * 128 + lane * 4;
        float4 val;
        if (uniform) {
            val.x = invS; val.y = invS; val.z = invS; val.w = invS;
        } else if (t < t_lo || t > t_hi) {
            val.x = 0.f; val.y = 0.f; val.z = 0.f; val.w = 0.f;
        } else {
            float* vv = (float*)&val;
#pragma unroll
            for (int u = 0; u < 4; u++) {
                int jj = c0 + u - jbase;
                unsigned sl = (unsigned)min(max(jj, 0), 31);
                float bandv = __shfl_sync(0xffffffffu, myw, sl);
                vv[u] = (jj >= 0 && jj < 15) ? bandv : 0.f;
            }
        }
        *(float4*)(wrow + c0) = val;
    }

    float r0, r1;
    if (uniform) {
        r0 = g_vsum[b * OD_ + h * HD_ + d0]     * invS;
        r1 = g_vsum[b * OD_ + h * HD_ + d0 + 1] * invS;
    } else {
        r0 = 0.f; r1 = 0.f;
#pragma unroll
        for (int jj = 0; jj < 15; jj++) {
            float wv = __shfl_sync(0xffffffffu, myw, jj);
            int j = jbase + jj;
            if (j >= 0 && j < S_ && wv != 0.f) {
                const float* vp = g_qvk + ((size_t)(b * S_ + j)) * NT_ + OD_ + h * HD_;
                r0 = fmaf(wv, vp[d0],     r0);
                r1 = fmaf(wv, vp[d0 + 1], r1);
            }
        }
    }

    size_t oidx = ((size_t)(b * S_ + i)) * OD_ + h * HD_ + d0;
    out_m[oidx]     = feats[oidx]     + r0;
    out_m[oidx + 1] = feats[oidx + 1] + r1;
}

// ---------------------------------------------------------------------------
extern "C" void kernel_launch(void* const* d_in, const int* in_sizes, int n_in,
                              void* d_out, int out_size)
{
    const float* feats = (const float*)d_in[0];
    const int*   mask  = (const int*)  d_in[1];
    const float* Wc    = (const float*)d_in[2];
    const float* bc    = (const float*)d_in[3];
    const float* Wv    = (const float*)d_in[4];
    const float* bv    = (const float*)d_in[5];

    float* out   = (float*)d_out;
    float* out_m = out;
    float* out_w = out + (size_t)B_ * S_ * OD_;

    static int smem_set = 0;
    if (!smem_set) {
        cudaFuncSetAttribute(gemm_tc, cudaFuncAttributeMaxDynamicSharedMemorySize, GEMM_SMEM);
        smem_set = 1;
    }

    conv_A<<<(M_ * ID_ / 4) / 256, 256>>>(feats);
    conv_W<<<dim3(NT_ / 32, ID_ / 32), dim3(32, 8)>>>(Wc, Wv);
    bias_k<<<(NT_ + 255) / 256, 256>>>(bc, bv);
    gemm_tc<<<dim3(NT_ / 128, M_ / 128), 128, GEMM_SMEM>>>();
    vsum_kernel<<<dim3(4, B_), 256>>>();
    attn_kernel<<<(B_ * H_ * S_) / 8, 256>>>(feats, mask, out_m, out_w);
}

// round 11
// speedup vs baseline: 3.3881x; 1.0354x over previous
#include <cuda_runtime.h>
#include <cuda_fp16.h>
#include <math.h>
#include <stdint.h>

// Problem constants
#define B_   8
#define S_   1024
#define ID_  1024
#define OD_  1024
#define H_   16
#define HD_  64
#define M_   8192          // B*S rows
#define NT_  3072          // q(1024) | v(1024) | k(1024) fused N
#define KHALF 7
#define TI   32            // attention rows per block

// ---------------- device scratch (no allocations allowed) -------------------
__device__ __align__(128) __half g_Ah[(size_t)M_ * ID_];
__device__ __align__(128) __half g_Al[(size_t)M_ * ID_];
__device__ __align__(128) __half g_Wt[(size_t)NT_ * ID_];    // W^T fp16 [n][k]
__device__ float g_bias[NT_];
__device__ __align__(128) float g_qvk[(size_t)M_ * NT_];     // [row][ q | v | k ]
__device__ float g_vsum[B_ * OD_];

// ---------------- PTX helpers (sm_80/90 portable only) ----------------------
__device__ __forceinline__ uint32_t smem_u32(const void* p) {
    uint32_t a;
    asm("{ .reg .u64 t; cvta.to.shared.u64 t, %1; cvt.u32.u64 %0, t; }" : "=r"(a) : "l"(p));
    return a;
}
__device__ __forceinline__ void cp_async16(uint32_t dst, const void* src) {
    asm volatile("cp.async.cg.shared.global [%0], [%1], 16;" :: "r"(dst), "l"(src));
}
#define CP_COMMIT() asm volatile("cp.async.commit_group;" ::: "memory")

__device__ __forceinline__ void ldsm4(uint32_t* r, uint32_t addr) {
    asm volatile("ldmatrix.sync.aligned.m8n8.x4.shared.b16 {%0,%1,%2,%3}, [%4];"
        : "=r"(r[0]), "=r"(r[1]), "=r"(r[2]), "=r"(r[3]) : "r"(addr));
}
__device__ __forceinline__ void mma_f16(float* c, const uint32_t* a, const uint32_t* b) {
    asm volatile("mma.sync.aligned.m16n8k16.row.col.f32.f16.f16.f32 "
        "{%0,%1,%2,%3}, {%4,%5,%6,%7}, {%8,%9}, {%0,%1,%2,%3};"
        : "+f"(c[0]), "+f"(c[1]), "+f"(c[2]), "+f"(c[3])
        : "r"(a[0]), "r"(a[1]), "r"(a[2]), "r"(a[3]), "r"(b[0]), "r"(b[1]));
}

// ---------------------------------------------------------------------------
// Conversion: A (m_feats) -> fp16 hi/lo, row-major [8192,1024]
// ---------------------------------------------------------------------------
__global__ __launch_bounds__(256) void conv_A(const float* __restrict__ A)
{
    size_t idx = (size_t)blockIdx.x * 256 + threadIdx.x;   // float4 index
    float4 a = ((const float4*)A)[idx];
    float v[4] = {a.x, a.y, a.z, a.w};
    __half h[4], l[4];
#pragma unroll
    for (int j = 0; j < 4; j++) {
        h[j] = __float2half_rn(v[j]);
        l[j] = __float2half_rn(v[j] - __half2float(h[j]));
    }
    ((uint2*)g_Ah)[idx] = *(uint2*)h;
    ((uint2*)g_Al)[idx] = *(uint2*)l;
}

// ---------------------------------------------------------------------------
// Conversion: W^T fp16. Wt[n][k] = (n<2048 ? Wc[k][n] : Wv[k][n-2048])
// ---------------------------------------------------------------------------
__global__ void conv_W(const float* __restrict__ Wc, const float* __restrict__ Wv)
{
    __shared__ float ts[32][33];
    int n0 = blockIdx.x * 32, k0 = blockIdx.y * 32;
    int tx = threadIdx.x, ty = threadIdx.y;
#pragma unroll
    for (int j = 0; j < 32; j += 8) {
        int k = k0 + ty + j, n = n0 + tx;
        float val = (n < 2 * OD_) ? Wc[(size_t)k * (2 * OD_) + n]
                                  : Wv[(size_t)k * OD_ + (n - 2 * OD_)];
        ts[ty + j][tx] = val;
    }
    __syncthreads();
#pragma unroll
    for (int j = 0; j < 32; j += 8) {
        float val = ts[tx][ty + j];
        size_t o = (size_t)(n0 + ty + j) * ID_ + (k0 + tx);
        g_Wt[o] = __float2half_rn(val);
    }
}

__global__ void bias_k(const float* __restrict__ bc, const float* __restrict__ bv)
{
    int i = blockIdx.x * 256 + threadIdx.x;
    if (i < NT_) g_bias[i] = (i < 2 * OD_) ? bc[i] : bv[i - 2 * OD_];
}

// ---------------------------------------------------------------------------
// HMMA GEMM: unchanged from round 9 (270us, tensor 72%).
// ---------------------------------------------------------------------------
#define AH_OFF 0
#define AL_OFF 8192
#define BF_OFF 16384
#define STAGE_SZ 24576
#define NSTAGE 4
#define GEMM_SMEM (NSTAGE * STAGE_SZ)
#define NCHUNK 32

__device__ __forceinline__ uint32_t tile_off(int row, int chunk) {
    return (uint32_t)(row * 64 + (((chunk ^ ((row >> 1) & 3)) & 3) << 4));
}

__device__ __forceinline__ void load_chunk(uint32_t stage, int m0, int n0, int c, int tid)
{
    const int k0 = c * 32;
    const char* srcs[3] = {
        (const char*)g_Ah + ((size_t)m0 * ID_ + k0) * 2,
        (const char*)g_Al + ((size_t)m0 * ID_ + k0) * 2,
        (const char*)g_Wt + ((size_t)n0 * ID_ + k0) * 2
    };
    const uint32_t offs[3] = {AH_OFF, AL_OFF, BF_OFF};
#pragma unroll
    for (int mi = 0; mi < 3; mi++) {
        const char* s = srcs[mi];
        uint32_t dbase = stage + offs[mi];
#pragma unroll
        for (int it = 0; it < 4; it++) {
            int e = tid + it * 128;          // 0..511
            int row = e >> 2, chunk = e & 3;
            cp_async16(dbase + tile_off(row, chunk), s + (size_t)row * 2048 + chunk * 16);
        }
    }
}

extern "C" __global__ void __launch_bounds__(128, 2) gemm_tc()
{
    extern __shared__ char smem[];
    const uint32_t sb = smem_u32(smem);
    const int tid = threadIdx.x, wid = tid >> 5, lane = tid & 31;
    const int n0 = blockIdx.x * 128, m0 = blockIdx.y * 128;
    const int wm = wid >> 1, wn = wid & 1;          // 2 x 2 warp grid, tile 64x64

    float acc[4][8][4];
#pragma unroll
    for (int a = 0; a < 4; a++)
#pragma unroll
        for (int b = 0; b < 8; b++)
#pragma unroll
            for (int d = 0; d < 4; d++) acc[a][b][d] = 0.f;

    const int a_row = wm * 64 + (lane & 15);
    const int a_sel = lane >> 4;
    const int b_n   = wn * 64 + ((lane >> 4) & 1) * 8 + (lane & 7);
    const int b_sel = (lane >> 3) & 1;

    load_chunk(sb + 0 * STAGE_SZ, m0, n0, 0, tid); CP_COMMIT();
    load_chunk(sb + 1 * STAGE_SZ, m0, n0, 1, tid); CP_COMMIT();
    load_chunk(sb + 2 * STAGE_SZ, m0, n0, 2, tid); CP_COMMIT();

    uint32_t buf = 0;

    for (int c = 0; c < NCHUNK; c++) {
        const int rem = NCHUNK - 1 - c;
        if (rem >= 2)      asm volatile("cp.async.wait_group 2;" ::: "memory");
        else if (rem == 1) asm volatile("cp.async.wait_group 1;" ::: "memory");
        else               asm volatile("cp.async.wait_group 0;" ::: "memory");
        __syncthreads();

        if (c + 3 < NCHUNK) {
            uint32_t nbuf = buf + 3; if (nbuf >= NSTAGE) nbuf -= NSTAGE;
            load_chunk(sb + nbuf * STAGE_SZ, m0, n0, c + 3, tid);
            CP_COMMIT();
        }

        const uint32_t stage = sb + buf * STAGE_SZ;
#pragma unroll
        for (int ks = 0; ks < 2; ks++) {
            uint32_t ah[4][4], al[4][4], bf[4][4];
#pragma unroll
            for (int mt = 0; mt < 4; mt++) {
                int row = a_row + mt * 16, ch = ks * 2 + a_sel;
                ldsm4(ah[mt], stage + AH_OFF + tile_off(row, ch));
                ldsm4(al[mt], stage + AL_OFF + tile_off(row, ch));
            }
#pragma unroll
            for (int nt = 0; nt < 4; nt++) {
                int n = b_n + nt * 16, ch = ks * 2 + b_sel;
                ldsm4(bf[nt], stage + BF_OFF + tile_off(n, ch));
            }
#pragma unroll
            for (int mt = 0; mt < 4; mt++) {
#pragma unroll
                for (int ng = 0; ng < 8; ng++) {
                    uint32_t b2[2] = { bf[ng >> 1][(ng & 1) * 2], bf[ng >> 1][(ng & 1) * 2 + 1] };
                    mma_f16(acc[mt][ng], ah[mt], b2);
                    mma_f16(acc[mt][ng], al[mt], b2);
                }
            }
        }

        buf++; if (buf >= NSTAGE) buf -= NSTAGE;
    }

    const int g  = lane >> 2;
    const int tc = (lane & 3) * 2;
    const int m0w = m0 + wm * 64, n0w = n0 + wn * 64;
#pragma unroll
    for (int mt = 0; mt < 4; mt++) {
#pragma unroll
        for (int r2 = 0; r2 < 2; r2++) {
            int row = m0w + mt * 16 + g + r2 * 8;
            float* orow = g_qvk + (size_t)row * NT_ + n0w;
#pragma unroll
            for (int ng = 0; ng < 8; ng++) {
                int col = ng * 8 + tc;
                float2 o;
                o.x = acc[mt][ng][r2 * 2 + 0] + g_bias[n0w + col];
                o.y = acc[mt][ng][r2 * 2 + 1] + g_bias[n0w + col + 1];
                *(float2*)(orow + col) = o;
            }
        }
    }
}

// ---------------------------------------------------------------------------
// vsum over seq of v (needed for fully-masked rows)
// ---------------------------------------------------------------------------
__global__ void vsum_kernel()
{
    int b  = blockIdx.y;
    int od = blockIdx.x * 256 + threadIdx.x;
    const float* vp = g_qvk + (size_t)b * S_ * NT_ + OD_ + od;
    float s = 0.f;
    for (int j = 0; j < S_; j++) s += vp[(size_t)j * NT_];
    g_vsum[b * OD_ + od] = s;
}

// ---------------------------------------------------------------------------
// Banded attention v2: block-tiled. One 512-thread block per (b, h, 32 rows).
// Stages k/q/v band in smem (transposed, padded strides -> conflict-free),
// computes scores with plain FMAs (no shuffle chains), coalesced w writes.
// ---------------------------------------------------------------------------
__global__ __launch_bounds__(512) void attn2_kernel(
    const float* __restrict__ feats,
    const int*   __restrict__ mask,
    float* __restrict__ out_m,
    float* __restrict__ out_w)
{
    __shared__ float skt[64][33];     // k transposed  [d][r]
    __shared__ float sqt[64][49];     // q transposed  [d][jq]
    __shared__ float svt[64][49];     // v transposed  [d][jq]
    __shared__ float sc[32][17];      // scores/weights [r][jj]
    __shared__ int   svalid[48];
    __shared__ int   suni[32];

    const int t    = threadIdx.x;
    const int blk  = blockIdx.x;          // (b*H + h)*(S/TI) + tile
    const int tile = blk & 31;
    const int bh   = blk >> 5;
    const int h    = bh & (H_ - 1);
    const int b    = bh >> 4;
    const int i0   = tile * TI;
    const int jlo  = i0 - KHALF;

    const float* qvk_b = g_qvk + (size_t)(b * S_) * NT_;

    // ---- load k (32 rows), transposed ----
    {
        int r = t >> 4, d0 = (t & 15) * 4;
        float4 kv = *(const float4*)(qvk_b + (size_t)(i0 + r) * NT_ + 2 * OD_ + h * HD_ + d0);
        skt[d0 + 0][r] = kv.x; skt[d0 + 1][r] = kv.y;
        skt[d0 + 2][r] = kv.z; skt[d0 + 3][r] = kv.w;
    }
    // ---- load q, v band (46 rows), transposed; zero OOB ----
    for (int e = t; e < 46 * 16; e += 512) {
        int jq = e >> 4, d0 = (e & 15) * 4;
        int j = jlo + jq;
        float4 qv = make_float4(0.f, 0.f, 0.f, 0.f);
        float4 vv = make_float4(0.f, 0.f, 0.f, 0.f);
        if (j >= 0 && j < S_) {
            qv = *(const float4*)(qvk_b + (size_t)j * NT_ + h * HD_ + d0);
            vv = *(const float4*)(qvk_b + (size_t)j * NT_ + OD_ + h * HD_ + d0);
        }
        sqt[d0 + 0][jq] = qv.x; sqt[d0 + 1][jq] = qv.y;
        sqt[d0 + 2][jq] = qv.z; sqt[d0 + 3][jq] = qv.w;
        svt[d0 + 0][jq] = vv.x; svt[d0 + 1][jq] = vv.y;
        svt[d0 + 2][jq] = vv.z; svt[d0 + 3][jq] = vv.w;
    }
    if (t < 48) {
        int j = jlo + t;
        svalid[t] = (j >= 0 && j < S_) ? (mask[b * S_ + j] != 0) : 0;
    }
    __syncthreads();

    // ---- scores: thread (r, jj) does a full 64-d dot from smem ----
    if (t < 480) {
        int r = t & 31, jj = t >> 5, jq = r + jj;
        float p0 = 0.f, p1 = 0.f, p2 = 0.f, p3 = 0.f;
#pragma unroll
        for (int d = 0; d < 64; d += 4) {
            p0 = fmaf(skt[d + 0][r], sqt[d + 0][jq], p0);
            p1 = fmaf(skt[d + 1][r], sqt[d + 1][jq], p1);
            p2 = fmaf(skt[d + 2][r], sqt[d + 2][jq], p2);
            p3 = fmaf(skt[d + 3][r], sqt[d + 3][jq], p3);
        }
        float p = (p0 + p1) + (p2 + p3);
        sc[r][jj] = svalid[jq] ? p * 0.125f : -1e9f;
    }
    __syncthreads();

    // ---- softmax: one lane per row ----
    if (t < 32) {
        int r = t;
        float mx = -1e9f;
#pragma unroll
        for (int jj = 0; jj < 15; jj++) mx = fmaxf(mx, sc[r][jj]);
        int uni = (mx == -1e9f);
        suni[r] = uni;
        float e[15], den = 0.f;
#pragma unroll
        for (int jj = 0; jj < 15; jj++) {
            e[jj] = uni ? 0.f : expf(sc[r][jj] - mx);
            den += e[jj];
        }
        float inv = uni ? 0.f : 1.f / den;
#pragma unroll
        for (int jj = 0; jj < 15; jj++) sc[r][jj] = e[jj] * inv;
    }
    __syncthreads();

    // ---- w write: 32 rows x 1024 cols, coalesced float4 ----
    const float invS = 1.0f / (float)S_;
    float* wbase = out_w + (size_t)bh * S_ * S_ + (size_t)i0 * S_;
#pragma unroll
    for (int p = 0; p < 16; p++) {
        int idx = p * 512 + t;
        int r = idx >> 8, c = (idx & 255) * 4;
        int jb = i0 + r - KHALF;     // global col of band start for this row
        float4 val;
        if (suni[r]) {
            val = make_float4(invS, invS, invS, invS);
        } else {
            float* vv = (float*)&val;
#pragma unroll
            for (int u = 0; u < 4; u++) {
                int jj = c + u - jb;
                int jjc = min(max(jj, 0), 14);
                float sv = sc[r][jjc];
                vv[u] = (jj >= 0 && jj < 15) ? sv : 0.f;
            }
        }
        *(float4*)(wbase + (size_t)r * S_ + c) = val;
    }

    // ---- r output: out_m = feats + sum_jj w * v ----
#pragma unroll
    for (int p = 0; p < 4; p++) {
        int idx = p * 512 + t;
        int r = idx >> 6, d = idx & 63;
        float acc;
        if (suni[r]) {
            acc = g_vsum[b * OD_ + h * HD_ + d] * invS;
        } else {
            acc = 0.f;
#pragma unroll
            for (int jj = 0; jj < 15; jj++)
                acc = fmaf(sc[r][jj], svt[d][r + jj], acc);
        }
        size_t oidx = (size_t)(b * S_ + i0 + r) * OD_ + h * HD_ + d;
        out_m[oidx] = feats[oidx] + acc;
    }
}

// ---------------------------------------------------------------------------
extern "C" void kernel_launch(void* const* d_in, const int* in_sizes, int n_in,
                              void* d_out, int out_size)
{
    const float* feats = (const float*)d_in[0];
    const int*   mask  = (const int*)  d_in[1];
    const float* Wc    = (const float*)d_in[2];
    const float* bc    = (const float*)d_in[3];
    const float* Wv    = (const float*)d_in[4];
    const float* bv    = (const float*)d_in[5];

    float* out   = (float*)d_out;
    float* out_m = out;
    float* out_w = out + (size_t)B_ * S_ * OD_;

    static int smem_set = 0;
    if (!smem_set) {
        cudaFuncSetAttribute(gemm_tc, cudaFuncAttributeMaxDynamicSharedMemorySize, GEMM_SMEM);
        smem_set = 1;
    }

    conv_A<<<(M_ * ID_ / 4) / 256, 256>>>(feats);
    conv_W<<<dim3(NT_ / 32, ID_ / 32), dim3(32, 8)>>>(Wc, Wv);
    bias_k<<<(NT_ + 255) / 256, 256>>>(bc, bv);
    gemm_tc<<<dim3(NT_ / 128, M_ / 128), 128, GEMM_SMEM>>>();
    vsum_kernel<<<dim3(4, B_), 256>>>();
    attn2_kernel<<<B_ * H_ * (S_ / TI), 512>>>(feats, mask, out_m, out_w);
}

// round 12
// speedup vs baseline: 3.4638x; 1.0224x over previous
#include <cuda_runtime.h>
#include <cuda_fp16.h>
#include <math.h>
#include <stdint.h>

// Problem constants
#define B_   8
#define S_   1024
#define ID_  1024
#define OD_  1024
#define H_   16
#define HD_  64
#define M_   8192          // B*S rows
#define NT_  3072          // q(1024) | v(1024) | k(1024) fused N
#define KHALF 7
#define TI   32            // attention rows per block

// ---------------- device scratch (no allocations allowed) -------------------
__device__ __align__(128) __half g_Ah[(size_t)M_ * ID_];
__device__ __align__(128) __half g_Al[(size_t)M_ * ID_];
__device__ __align__(128) __half g_Wt[(size_t)NT_ * ID_];    // W^T fp16 [n][k]
__device__ float g_bias[NT_];
__device__ __align__(128) float g_qvk[(size_t)M_ * NT_];     // [row][ q | v | k ]
__device__ float g_vsum[B_ * OD_];

// ---------------- PTX helpers (sm_80/90 portable only) ----------------------
__device__ __forceinline__ uint32_t smem_u32(const void* p) {
    uint32_t a;
    asm("{ .reg .u64 t; cvta.to.shared.u64 t, %1; cvt.u32.u64 %0, t; }" : "=r"(a) : "l"(p));
    return a;
}
__device__ __forceinline__ void cp_async16(uint32_t dst, const void* src) {
    asm volatile("cp.async.cg.shared.global [%0], [%1], 16;" :: "r"(dst), "l"(src));
}
#define CP_COMMIT() asm volatile("cp.async.commit_group;" ::: "memory")

__device__ __forceinline__ void ldsm4(uint32_t* r, uint32_t addr) {
    asm volatile("ldmatrix.sync.aligned.m8n8.x4.shared.b16 {%0,%1,%2,%3}, [%4];"
        : "=r"(r[0]), "=r"(r[1]), "=r"(r[2]), "=r"(r[3]) : "r"(addr));
}
__device__ __forceinline__ void mma_f16(float* c, const uint32_t* a, const uint32_t* b) {
    asm volatile("mma.sync.aligned.m16n8k16.row.col.f32.f16.f16.f32 "
        "{%0,%1,%2,%3}, {%4,%5,%6,%7}, {%8,%9}, {%0,%1,%2,%3};"
        : "+f"(c[0]), "+f"(c[1]), "+f"(c[2]), "+f"(c[3])
        : "r"(a[0]), "r"(a[1]), "r"(a[2]), "r"(a[3]), "r"(b[0]), "r"(b[1]));
}

// ---------------------------------------------------------------------------
// Conversion: A (m_feats) -> fp16 hi/lo, row-major [8192,1024]
// ---------------------------------------------------------------------------
__global__ __launch_bounds__(256) void conv_A(const float* __restrict__ A)
{
    size_t idx = (size_t)blockIdx.x * 256 + threadIdx.x;   // float4 index
    float4 a = ((const float4*)A)[idx];
    float v[4] = {a.x, a.y, a.z, a.w};
    __half h[4], l[4];
#pragma unroll
    for (int j = 0; j < 4; j++) {
        h[j] = __float2half_rn(v[j]);
        l[j] = __float2half_rn(v[j] - __half2float(h[j]));
    }
    ((uint2*)g_Ah)[idx] = *(uint2*)h;
    ((uint2*)g_Al)[idx] = *(uint2*)l;
}

// ---------------------------------------------------------------------------
// Conversion: W^T fp16. Wt[n][k] = (n<2048 ? Wc[k][n] : Wv[k][n-2048])
// ---------------------------------------------------------------------------
__global__ void conv_W(const float* __restrict__ Wc, const float* __restrict__ Wv)
{
    __shared__ float ts[32][33];
    int n0 = blockIdx.x * 32, k0 = blockIdx.y * 32;
    int tx = threadIdx.x, ty = threadIdx.y;
#pragma unroll
    for (int j = 0; j < 32; j += 8) {
        int k = k0 + ty + j, n = n0 + tx;
        float val = (n < 2 * OD_) ? Wc[(size_t)k * (2 * OD_) + n]
                                  : Wv[(size_t)k * OD_ + (n - 2 * OD_)];
        ts[ty + j][tx] = val;
    }
    __syncthreads();
#pragma unroll
    for (int j = 0; j < 32; j += 8) {
        float val = ts[tx][ty + j];
        size_t o = (size_t)(n0 + ty + j) * ID_ + (k0 + tx);
        g_Wt[o] = __float2half_rn(val);
    }
}

// bias table + vsum init (vsum starts at 1024 * v-bias; gemm atomics add dots)
__global__ void bias_k(const float* __restrict__ bc, const float* __restrict__ bv)
{
    int i = blockIdx.x * 256 + threadIdx.x;    // 0..8191
    if (i < NT_) g_bias[i] = (i < 2 * OD_) ? bc[i] : bv[i - 2 * OD_];
    int od = i & (OD_ - 1);
    g_vsum[i] = 1024.f * bc[OD_ + od];
}

// ---------------------------------------------------------------------------
// HMMA GEMM: fp16x2 split (A hi/lo, W single). CTA 128x128, BK=32, 4 buffers,
// ONE sync per 2 chunks (16 barriers). 4 warps (2x2), warp tile 64x64.
// v-region CTAs also accumulate column sums into g_vsum (replaces vsum kernel).
// ---------------------------------------------------------------------------
#define AH_OFF 0
#define AL_OFF 8192
#define BF_OFF 16384
#define STAGE_SZ 24576
#define NSTAGE 4
#define GEMM_SMEM (NSTAGE * STAGE_SZ)
#define NCHUNK 32

__device__ __forceinline__ uint32_t tile_off(int row, int chunk) {
    return (uint32_t)(row * 64 + (((chunk ^ ((row >> 1) & 3)) & 3) << 4));
}

__device__ __forceinline__ void load_chunk(uint32_t stage, int m0, int n0, int c, int tid)
{
    const int k0 = c * 32;
    const char* srcs[3] = {
        (const char*)g_Ah + ((size_t)m0 * ID_ + k0) * 2,
        (const char*)g_Al + ((size_t)m0 * ID_ + k0) * 2,
        (const char*)g_Wt + ((size_t)n0 * ID_ + k0) * 2
    };
    const uint32_t offs[3] = {AH_OFF, AL_OFF, BF_OFF};
#pragma unroll
    for (int mi = 0; mi < 3; mi++) {
        const char* s = srcs[mi];
        uint32_t dbase = stage + offs[mi];
#pragma unroll
        for (int it = 0; it < 4; it++) {
            int e = tid + it * 128;          // 0..511
            int row = e >> 2, chunk = e & 3;
            cp_async16(dbase + tile_off(row, chunk), s + (size_t)row * 2048 + chunk * 16);
        }
    }
}

extern "C" __global__ void __launch_bounds__(128, 2) gemm_tc()
{
    extern __shared__ char smem[];
    const uint32_t sb = smem_u32(smem);
    const int tid = threadIdx.x, wid = tid >> 5, lane = tid & 31;
    const int n0 = blockIdx.x * 128, m0 = blockIdx.y * 128;
    const int wm = wid >> 1, wn = wid & 1;          // 2 x 2 warp grid, tile 64x64

    float acc[4][8][4];
#pragma unroll
    for (int a = 0; a < 4; a++)
#pragma unroll
        for (int b = 0; b < 8; b++)
#pragma unroll
            for (int d = 0; d < 4; d++) acc[a][b][d] = 0.f;

    const int a_row = wm * 64 + (lane & 15);
    const int a_sel = lane >> 4;
    const int b_n   = wn * 64 + ((lane >> 4) & 1) * 8 + (lane & 7);
    const int b_sel = (lane >> 3) & 1;

    // prologue: chunks 0,1 into buffers 0,1
    load_chunk(sb + 0 * STAGE_SZ, m0, n0, 0, tid); CP_COMMIT();
    load_chunk(sb + 1 * STAGE_SZ, m0, n0, 1, tid); CP_COMMIT();

    for (int s = 0; s < NCHUNK / 2; s++) {
        const int c0 = 2 * s;
        // pending groups at this point: exactly chunks c0, c0+1
        asm volatile("cp.async.wait_group 0;" ::: "memory");
        __syncthreads();   // + all warps done with chunks c0-2, c0-1

        if (c0 + 2 < NCHUNK) {
            load_chunk(sb + ((c0 + 2) & 3) * STAGE_SZ, m0, n0, c0 + 2, tid); CP_COMMIT();
            load_chunk(sb + ((c0 + 3) & 3) * STAGE_SZ, m0, n0, c0 + 3, tid); CP_COMMIT();
        }

#pragma unroll
        for (int cc = 0; cc < 2; cc++) {
            const uint32_t stage = sb + ((c0 + cc) & 3) * STAGE_SZ;
#pragma unroll
            for (int ks = 0; ks < 2; ks++) {
                uint32_t ah[4][4], al[4][4], bf[4][4];
#pragma unroll
                for (int mt = 0; mt < 4; mt++) {
                    int row = a_row + mt * 16, ch = ks * 2 + a_sel;
                    ldsm4(ah[mt], stage + AH_OFF + tile_off(row, ch));
                    ldsm4(al[mt], stage + AL_OFF + tile_off(row, ch));
                }
#pragma unroll
                for (int nt = 0; nt < 4; nt++) {
                    int n = b_n + nt * 16, ch = ks * 2 + b_sel;
                    ldsm4(bf[nt], stage + BF_OFF + tile_off(n, ch));
                }
#pragma unroll
                for (int mt = 0; mt < 4; mt++) {
#pragma unroll
                    for (int ng = 0; ng < 8; ng++) {
                        uint32_t b2[2] = { bf[ng >> 1][(ng & 1) * 2], bf[ng >> 1][(ng & 1) * 2 + 1] };
                        mma_f16(acc[mt][ng], ah[mt], b2);
                        mma_f16(acc[mt][ng], al[mt], b2);
                    }
                }
            }
        }
    }

    // epilogue: write acc + bias to g_qvk
    const int g  = lane >> 2;
    const int tc = (lane & 3) * 2;
    const int m0w = m0 + wm * 64, n0w = n0 + wn * 64;
#pragma unroll
    for (int mt = 0; mt < 4; mt++) {
#pragma unroll
        for (int r2 = 0; r2 < 2; r2++) {
            int row = m0w + mt * 16 + g + r2 * 8;
            float* orow = g_qvk + (size_t)row * NT_ + n0w;
#pragma unroll
            for (int ng = 0; ng < 8; ng++) {
                int col = ng * 8 + tc;
                float2 o;
                o.x = acc[mt][ng][r2 * 2 + 0] + g_bias[n0w + col];
                o.y = acc[mt][ng][r2 * 2 + 1] + g_bias[n0w + col + 1];
                *(float2*)(orow + col) = o;
            }
        }
    }

    // fused vsum: v-region CTAs accumulate column sums (dots only; bias seeded)
    if (n0 >= OD_ && n0 < 2 * OD_) {
        const int bb = m0 >> 10;   // batch index
#pragma unroll
        for (int ng = 0; ng < 8; ng++) {
            float s0 = 0.f, s1 = 0.f;
#pragma unroll
            for (int mt = 0; mt < 4; mt++) {
                s0 += acc[mt][ng][0] + acc[mt][ng][2];
                s1 += acc[mt][ng][1] + acc[mt][ng][3];
            }
            // reduce across the 8 row-groups (lanes with same lane&3)
#pragma unroll
            for (int off = 16; off >= 4; off >>= 1) {
                s0 += __shfl_xor_sync(0xffffffffu, s0, off);
                s1 += __shfl_xor_sync(0xffffffffu, s1, off);
            }
            if (lane < 4) {
                int col = n0w - OD_ + ng * 8 + lane * 2;
                atomicAdd(&g_vsum[bb * OD_ + col],     s0);
                atomicAdd(&g_vsum[bb * OD_ + col + 1], s1);
            }
        }
    }
}

// ---------------------------------------------------------------------------
// Banded attention v2: block-tiled. One 512-thread block per (b, h, 32 rows).
// ---------------------------------------------------------------------------
__global__ __launch_bounds__(512) void attn2_kernel(
    const float* __restrict__ feats,
    const int*   __restrict__ mask,
    float* __restrict__ out_m,
    float* __restrict__ out_w)
{
    __shared__ float skt[64][33];     // k transposed  [d][r]
    __shared__ float sqt[64][49];     // q transposed  [d][jq]
    __shared__ float svt[64][49];     // v transposed  [d][jq]
    __shared__ float sc[32][17];      // scores/weights [r][jj]
    __shared__ int   svalid[48];
    __shared__ int   suni[32];

    const int t    = threadIdx.x;
    const int blk  = blockIdx.x;          // (b*H + h)*(S/TI) + tile
    const int tile = blk & 31;
    const int bh   = blk >> 5;
    const int h    = bh & (H_ - 1);
    const int b    = bh >> 4;
    const int i0   = tile * TI;
    const int jlo  = i0 - KHALF;

    const float* qvk_b = g_qvk + (size_t)(b * S_) * NT_;

    // ---- load k (32 rows), transposed ----
    {
        int r = t >> 4, d0 = (t & 15) * 4;
        float4 kv = *(const float4*)(qvk_b + (size_t)(i0 + r) * NT_ + 2 * OD_ + h * HD_ + d0);
        skt[d0 + 0][r] = kv.x; skt[d0 + 1][r] = kv.y;
        skt[d0 + 2][r] = kv.z; skt[d0 + 3][r] = kv.w;
    }
    // ---- load q, v band (46 rows), transposed; zero OOB ----
    for (int e = t; e < 46 * 16; e += 512) {
        int jq = e >> 4, d0 = (e & 15) * 4;
        int j = jlo + jq;
        float4 qv = make_float4(0.f, 0.f, 0.f, 0.f);
        float4 vv = make_float4(0.f, 0.f, 0.f, 0.f);
        if (j >= 0 && j < S_) {
            qv = *(const float4*)(qvk_b + (size_t)j * NT_ + h * HD_ + d0);
            vv = *(const float4*)(qvk_b + (size_t)j * NT_ + OD_ + h * HD_ + d0);
        }
        sqt[d0 + 0][jq] = qv.x; sqt[d0 + 1][jq] = qv.y;
        sqt[d0 + 2][jq] = qv.z; sqt[d0 + 3][jq] = qv.w;
        svt[d0 + 0][jq] = vv.x; svt[d0 + 1][jq] = vv.y;
        svt[d0 + 2][jq] = vv.z; svt[d0 + 3][jq] = vv.w;
    }
    if (t < 48) {
        int j = jlo + t;
        svalid[t] = (j >= 0 && j < S_) ? (mask[b * S_ + j] != 0) : 0;
    }
    __syncthreads();

    // ---- scores: thread (r, jj) does a full 64-d dot from smem ----
    if (t < 480) {
        int r = t & 31, jj = t >> 5, jq = r + jj;
        float p0 = 0.f, p1 = 0.f, p2 = 0.f, p3 = 0.f;
#pragma unroll
        for (int d = 0; d < 64; d += 4) {
            p0 = fmaf(skt[d + 0][r], sqt[d + 0][jq], p0);
            p1 = fmaf(skt[d + 1][r], sqt[d + 1][jq], p1);
            p2 = fmaf(skt[d + 2][r], sqt[d + 2][jq], p2);
            p3 = fmaf(skt[d + 3][r], sqt[d + 3][jq], p3);
        }
        float p = (p0 + p1) + (p2 + p3);
        sc[r][jj] = svalid[jq] ? p * 0.125f : -1e9f;
    }
    __syncthreads();

    // ---- softmax: one lane per row ----
    if (t < 32) {
        int r = t;
        float mx = -1e9f;
#pragma unroll
        for (int jj = 0; jj < 15; jj++) mx = fmaxf(mx, sc[r][jj]);
        int uni = (mx == -1e9f);
        suni[r] = uni;
        float e[15], den = 0.f;
#pragma unroll
        for (int jj = 0; jj < 15; jj++) {
            e[jj] = uni ? 0.f : expf(sc[r][jj] - mx);
            den += e[jj];
        }
        float inv = uni ? 0.f : 1.f / den;
#pragma unroll
        for (int jj = 0; jj < 15; jj++) sc[r][jj] = e[jj] * inv;
    }
    __syncthreads();

    // ---- w write: 32 rows x 1024 cols, coalesced float4, streaming ----
    const float invS = 1.0f / (float)S_;
    float* wbase = out_w + (size_t)bh * S_ * S_ + (size_t)i0 * S_;
#pragma unroll
    for (int p = 0; p < 16; p++) {
        int idx = p * 512 + t;
        int r = idx >> 8, c = (idx & 255) * 4;
        int jb = i0 + r - KHALF;     // global col of band start for this row
        float4 val;
        if (suni[r]) {
            val = make_float4(invS, invS, invS, invS);
        } else {
            float* vv = (float*)&val;
#pragma unroll
            for (int u = 0; u < 4; u++) {
                int jj = c + u - jb;
                int jjc = min(max(jj, 0), 14);
                float sv = sc[r][jjc];
                vv[u] = (jj >= 0 && jj < 15) ? sv : 0.f;
            }
        }
        __stwt((float4*)(wbase + (size_t)r * S_ + c), val);
    }

    // ---- r output: out_m = feats + sum_jj w * v ----
#pragma unroll
    for (int p = 0; p < 4; p++) {
        int idx = p * 512 + t;
        int r = idx >> 6, d = idx & 63;
        float acc;
        if (suni[r]) {
            acc = g_vsum[b * OD_ + h * HD_ + d] * invS;
        } else {
            acc = 0.f;
#pragma unroll
            for (int jj = 0; jj < 15; jj++)
                acc = fmaf(sc[r][jj], svt[d][r + jj], acc);
        }
        size_t oidx = (size_t)(b * S_ + i0 + r) * OD_ + h * HD_ + d;
        out_m[oidx] = feats[oidx] + acc;
    }
}

// ---------------------------------------------------------------------------
extern "C" void kernel_launch(void* const* d_in, const int* in_sizes, int n_in,
                              void* d_out, int out_size)
{
    const float* feats = (const float*)d_in[0];
    const int*   mask  = (const int*)  d_in[1];
    const float* Wc    = (const float*)d_in[2];
    const float* bc    = (const float*)d_in[3];
    const float* Wv    = (const float*)d_in[4];
    const float* bv    = (const float*)d_in[5];

    float* out   = (float*)d_out;
    float* out_m = out;
    float* out_w = out + (size_t)B_ * S_ * OD_;

    static int smem_set = 0;
    if (!smem_set) {
        cudaFuncSetAttribute(gemm_tc, cudaFuncAttributeMaxDynamicSharedMemorySize, GEMM_SMEM);
        smem_set = 1;
    }

    conv_A<<<(M_ * ID_ / 4) / 256, 256>>>(feats);
    conv_W<<<dim3(NT_ / 32, ID_ / 32), dim3(32, 8)>>>(Wc, Wv);
    bias_k<<<(B_ * OD_) / 256, 256>>>(bc, bv);
    gemm_tc<<<dim3(NT_ / 128, M_ / 128), 128, GEMM_SMEM>>>();
    attn2_kernel<<<B_ * H_ * (S_ / TI), 512>>>(feats, mask, out_m, out_w);
}

// round 13
// speedup vs baseline: 3.6651x; 1.0581x over previous
#include <cuda_runtime.h>
#include <cuda_fp16.h>
#include <math.h>
#include <stdint.h>

// Problem constants
#define B_   8
#define S_   1024
#define ID_  1024
#define OD_  1024
#define H_   16
#define HD_  64
#define M_   8192          // B*S rows
#define NT_  3072          // q(1024) | v(1024) | k(1024) fused N
#define KHALF 7
#define TI   32            // attention rows per block

// ---------------- device scratch (no allocations allowed) -------------------
__device__ __align__(128) __half g_Ah[(size_t)M_ * ID_];
__device__ __align__(128) __half g_Al[(size_t)M_ * ID_];
__device__ __align__(128) __half g_Wt[(size_t)NT_ * ID_];    // W^T fp16 [n][k]
__device__ float g_bias[NT_];
__device__ __align__(128) float g_qvk[(size_t)M_ * NT_];     // [row][ q | v | k ]
__device__ float g_vsum[B_ * OD_];

// ---------------- PTX helpers (sm_80/90 portable only) ----------------------
__device__ __forceinline__ uint32_t smem_u32(const void* p) {
    uint32_t a;
    asm("{ .reg .u64 t; cvta.to.shared.u64 t, %1; cvt.u32.u64 %0, t; }" : "=r"(a) : "l"(p));
    return a;
}
__device__ __forceinline__ void cp_async16(uint32_t dst, const void* src) {
    asm volatile("cp.async.cg.shared.global [%0], [%1], 16;" :: "r"(dst), "l"(src));
}
#define CP_COMMIT() asm volatile("cp.async.commit_group;" ::: "memory")

__device__ __forceinline__ void ldsm4(uint32_t* r, uint32_t addr) {
    asm volatile("ldmatrix.sync.aligned.m8n8.x4.shared.b16 {%0,%1,%2,%3}, [%4];"
        : "=r"(r[0]), "=r"(r[1]), "=r"(r[2]), "=r"(r[3]) : "r"(addr));
}
__device__ __forceinline__ void mma_f16(float* c, const uint32_t* a, const uint32_t* b) {
    asm volatile("mma.sync.aligned.m16n8k16.row.col.f32.f16.f16.f32 "
        "{%0,%1,%2,%3}, {%4,%5,%6,%7}, {%8,%9}, {%0,%1,%2,%3};"
        : "+f"(c[0]), "+f"(c[1]), "+f"(c[2]), "+f"(c[3])
        : "r"(a[0]), "r"(a[1]), "r"(a[2]), "r"(a[3]), "r"(b[0]), "r"(b[1]));
}

// ---------------------------------------------------------------------------
// Conversion: A (m_feats) -> fp16 hi/lo, row-major [8192,1024]
// ---------------------------------------------------------------------------
__global__ __launch_bounds__(256) void conv_A(const float* __restrict__ A)
{
    size_t idx = (size_t)blockIdx.x * 256 + threadIdx.x;   // float4 index
    float4 a = ((const float4*)A)[idx];
    float v[4] = {a.x, a.y, a.z, a.w};
    __half h[4], l[4];
#pragma unroll
    for (int j = 0; j < 4; j++) {
        h[j] = __float2half_rn(v[j]);
        l[j] = __float2half_rn(v[j] - __half2float(h[j]));
    }
    ((uint2*)g_Ah)[idx] = *(uint2*)h;
    ((uint2*)g_Al)[idx] = *(uint2*)l;
}

// ---------------------------------------------------------------------------
// Conversion: W^T fp16. Wt[n][k] = (n<2048 ? Wc[k][n] : Wv[k][n-2048])
// ---------------------------------------------------------------------------
__global__ void conv_W(const float* __restrict__ Wc, const float* __restrict__ Wv)
{
    __shared__ float ts[32][33];
    int n0 = blockIdx.x * 32, k0 = blockIdx.y * 32;
    int tx = threadIdx.x, ty = threadIdx.y;
#pragma unroll
    for (int j = 0; j < 32; j += 8) {
        int k = k0 + ty + j, n = n0 + tx;
        float val = (n < 2 * OD_) ? Wc[(size_t)k * (2 * OD_) + n]
                                  : Wv[(size_t)k * OD_ + (n - 2 * OD_)];
        ts[ty + j][tx] = val;
    }
    __syncthreads();
#pragma unroll
    for (int j = 0; j < 32; j += 8) {
        float val = ts[tx][ty + j];
        size_t o = (size_t)(n0 + ty + j) * ID_ + (k0 + tx);
        g_Wt[o] = __float2half_rn(val);
    }
}

// bias table + vsum init (vsum starts at 1024 * v-bias; gemm atomics add dots)
__global__ void bias_k(const float* __restrict__ bc, const float* __restrict__ bv)
{
    int i = blockIdx.x * 256 + threadIdx.x;    // 0..8191
    if (i < NT_) g_bias[i] = (i < 2 * OD_) ? bc[i] : bv[i - 2 * OD_];
    int od = i & (OD_ - 1);
    g_vsum[i] = 1024.f * bc[OD_ + od];
}

// ---------------------------------------------------------------------------
// HMMA GEMM: fp16x2 split (A hi/lo, W single). CTA 128x128, BK=32, 4 buffers,
// one load + wait_group 2 + one sync per chunk (round-11 schedule: best
// measured, 260us / tensor 72%). 4 warps (2x2), warp tile 64x64.
// v-region CTAs also accumulate column sums into g_vsum (fused vsum).
// ---------------------------------------------------------------------------
#define AH_OFF 0
#define AL_OFF 8192
#define BF_OFF 16384
#define STAGE_SZ 24576
#define NSTAGE 4
#define GEMM_SMEM (NSTAGE * STAGE_SZ)
#define NCHUNK 32

__device__ __forceinline__ uint32_t tile_off(int row, int chunk) {
    return (uint32_t)(row * 64 + (((chunk ^ ((row >> 1) & 3)) & 3) << 4));
}

__device__ __forceinline__ void load_chunk(uint32_t stage, int m0, int n0, int c, int tid)
{
    const int k0 = c * 32;
    const char* srcs[3] = {
        (const char*)g_Ah + ((size_t)m0 * ID_ + k0) * 2,
        (const char*)g_Al + ((size_t)m0 * ID_ + k0) * 2,
        (const char*)g_Wt + ((size_t)n0 * ID_ + k0) * 2
    };
    const uint32_t offs[3] = {AH_OFF, AL_OFF, BF_OFF};
#pragma unroll
    for (int mi = 0; mi < 3; mi++) {
        const char* s = srcs[mi];
        uint32_t dbase = stage + offs[mi];
#pragma unroll
        for (int it = 0; it < 4; it++) {
            int e = tid + it * 128;          // 0..511
            int row = e >> 2, chunk = e & 3;
            cp_async16(dbase + tile_off(row, chunk), s + (size_t)row * 2048 + chunk * 16);
        }
    }
}

extern "C" __global__ void __launch_bounds__(128, 2) gemm_tc()
{
    extern __shared__ char smem[];
    const uint32_t sb = smem_u32(smem);
    const int tid = threadIdx.x, wid = tid >> 5, lane = tid & 31;
    const int n0 = blockIdx.x * 128, m0 = blockIdx.y * 128;
    const int wm = wid >> 1, wn = wid & 1;          // 2 x 2 warp grid, tile 64x64

    float acc[4][8][4];
#pragma unroll
    for (int a = 0; a < 4; a++)
#pragma unroll
        for (int b = 0; b < 8; b++)
#pragma unroll
            for (int d = 0; d < 4; d++) acc[a][b][d] = 0.f;

    const int a_row = wm * 64 + (lane & 15);
    const int a_sel = lane >> 4;
    const int b_n   = wn * 64 + ((lane >> 4) & 1) * 8 + (lane & 7);
    const int b_sel = (lane >> 3) & 1;

    // prologue: chunks 0,1,2 into buffers 0,1,2
    load_chunk(sb + 0 * STAGE_SZ, m0, n0, 0, tid); CP_COMMIT();
    load_chunk(sb + 1 * STAGE_SZ, m0, n0, 1, tid); CP_COMMIT();
    load_chunk(sb + 2 * STAGE_SZ, m0, n0, 2, tid); CP_COMMIT();

    uint32_t buf = 0;

    for (int c = 0; c < NCHUNK; c++) {
        const int rem = NCHUNK - 1 - c;
        if (rem >= 2)      asm volatile("cp.async.wait_group 2;" ::: "memory");
        else if (rem == 1) asm volatile("cp.async.wait_group 1;" ::: "memory");
        else               asm volatile("cp.async.wait_group 0;" ::: "memory");
        __syncthreads();   // chunk c resident + all warps done with c-1

        if (c + 3 < NCHUNK) {
            uint32_t nbuf = buf + 3; if (nbuf >= NSTAGE) nbuf -= NSTAGE;
            load_chunk(sb + nbuf * STAGE_SZ, m0, n0, c + 3, tid);
            CP_COMMIT();
        }

        const uint32_t stage = sb + buf * STAGE_SZ;
#pragma unroll
        for (int ks = 0; ks < 2; ks++) {
            uint32_t ah[4][4], al[4][4], bf[4][4];
#pragma unroll
            for (int mt = 0; mt < 4; mt++) {
                int row = a_row + mt * 16, ch = ks * 2 + a_sel;
                ldsm4(ah[mt], stage + AH_OFF + tile_off(row, ch));
                ldsm4(al[mt], stage + AL_OFF + tile_off(row, ch));
            }
#pragma unroll
            for (int nt = 0; nt < 4; nt++) {
                int n = b_n + nt * 16, ch = ks * 2 + b_sel;
                ldsm4(bf[nt], stage + BF_OFF + tile_off(n, ch));
            }
#pragma unroll
            for (int mt = 0; mt < 4; mt++) {
#pragma unroll
                for (int ng = 0; ng < 8; ng++) {
                    uint32_t b2[2] = { bf[ng >> 1][(ng & 1) * 2], bf[ng >> 1][(ng & 1) * 2 + 1] };
                    mma_f16(acc[mt][ng], ah[mt], b2);
                    mma_f16(acc[mt][ng], al[mt], b2);
                }
            }
        }

        buf++; if (buf >= NSTAGE) buf -= NSTAGE;
    }

    // epilogue: write acc + bias to g_qvk
    const int g  = lane >> 2;
    const int tc = (lane & 3) * 2;
    const int m0w = m0 + wm * 64, n0w = n0 + wn * 64;
#pragma unroll
    for (int mt = 0; mt < 4; mt++) {
#pragma unroll
        for (int r2 = 0; r2 < 2; r2++) {
            int row = m0w + mt * 16 + g + r2 * 8;
            float* orow = g_qvk + (size_t)row * NT_ + n0w;
#pragma unroll
            for (int ng = 0; ng < 8; ng++) {
                int col = ng * 8 + tc;
                float2 o;
                o.x = acc[mt][ng][r2 * 2 + 0] + g_bias[n0w + col];
                o.y = acc[mt][ng][r2 * 2 + 1] + g_bias[n0w + col + 1];
                *(float2*)(orow + col) = o;
            }
        }
    }

    // fused vsum: v-region CTAs accumulate column sums (dots only; bias seeded)
    if (n0 >= OD_ && n0 < 2 * OD_) {
        const int bb = m0 >> 10;   // batch index
#pragma unroll
        for (int ng = 0; ng < 8; ng++) {
            float s0 = 0.f, s1 = 0.f;
#pragma unroll
            for (int mt = 0; mt < 4; mt++) {
                s0 += acc[mt][ng][0] + acc[mt][ng][2];
                s1 += acc[mt][ng][1] + acc[mt][ng][3];
            }
            // reduce across the 8 row-groups (lanes with same lane&3)
#pragma unroll
            for (int off = 16; off >= 4; off >>= 1) {
                s0 += __shfl_xor_sync(0xffffffffu, s0, off);
                s1 += __shfl_xor_sync(0xffffffffu, s1, off);
            }
            if (lane < 4) {
                int col = n0w - OD_ + ng * 8 + lane * 2;
                atomicAdd(&g_vsum[bb * OD_ + col],     s0);
                atomicAdd(&g_vsum[bb * OD_ + col + 1], s1);
            }
        }
    }
}

// ---------------------------------------------------------------------------
// Banded attention v2: block-tiled. One 512-thread block per (b, h, 32 rows).
// ---------------------------------------------------------------------------
__global__ __launch_bounds__(512) void attn2_kernel(
    const float* __restrict__ feats,
    const int*   __restrict__ mask,
    float* __restrict__ out_m,
    float* __restrict__ out_w)
{
    __shared__ float skt[64][33];     // k transposed  [d][r]
    __shared__ float sqt[64][49];     // q transposed  [d][jq]
    __shared__ float svt[64][49];     // v transposed  [d][jq]
    __shared__ float sc[32][17];      // scores/weights [r][jj]
    __shared__ int   svalid[48];
    __shared__ int   suni[32];

    const int t    = threadIdx.x;
    const int blk  = blockIdx.x;          // (b*H + h)*(S/TI) + tile
    const int tile = blk & 31;
    const int bh   = blk >> 5;
    const int h    = bh & (H_ - 1);
    const int b    = bh >> 4;
    const int i0   = tile * TI;
    const int jlo  = i0 - KHALF;

    const float* qvk_b = g_qvk + (size_t)(b * S_) * NT_;

    // ---- load k (32 rows), transposed ----
    {
        int r = t >> 4, d0 = (t & 15) * 4;
        float4 kv = *(const float4*)(qvk_b + (size_t)(i0 + r) * NT_ + 2 * OD_ + h * HD_ + d0);
        skt[d0 + 0][r] = kv.x; skt[d0 + 1][r] = kv.y;
        skt[d0 + 2][r] = kv.z; skt[d0 + 3][r] = kv.w;
    }
    // ---- load q, v band (46 rows), transposed; zero OOB ----
    for (int e = t; e < 46 * 16; e += 512) {
        int jq = e >> 4, d0 = (e & 15) * 4;
        int j = jlo + jq;
        float4 qv = make_float4(0.f, 0.f, 0.f, 0.f);
        float4 vv = make_float4(0.f, 0.f, 0.f, 0.f);
        if (j >= 0 && j < S_) {
            qv = *(const float4*)(qvk_b + (size_t)j * NT_ + h * HD_ + d0);
            vv = *(const float4*)(qvk_b + (size_t)j * NT_ + OD_ + h * HD_ + d0);
        }
        sqt[d0 + 0][jq] = qv.x; sqt[d0 + 1][jq] = qv.y;
        sqt[d0 + 2][jq] = qv.z; sqt[d0 + 3][jq] = qv.w;
        svt[d0 + 0][jq] = vv.x; svt[d0 + 1][jq] = vv.y;
        svt[d0 + 2][jq] = vv.z; svt[d0 + 3][jq] = vv.w;
    }
    if (t < 48) {
        int j = jlo + t;
        svalid[t] = (j >= 0 && j < S_) ? (mask[b * S_ + j] != 0) : 0;
    }
    __syncthreads();

    // ---- scores: thread (r, jj) does a full 64-d dot from smem ----
    if (t < 480) {
        int r = t & 31, jj = t >> 5, jq = r + jj;
        float p0 = 0.f, p1 = 0.f, p2 = 0.f, p3 = 0.f;
#pragma unroll
        for (int d = 0; d < 64; d += 4) {
            p0 = fmaf(skt[d + 0][r], sqt[d + 0][jq], p0);
            p1 = fmaf(skt[d + 1][r], sqt[d + 1][jq], p1);
            p2 = fmaf(skt[d + 2][r], sqt[d + 2][jq], p2);
            p3 = fmaf(skt[d + 3][r], sqt[d + 3][jq], p3);
        }
        float p = (p0 + p1) + (p2 + p3);
        sc[r][jj] = svalid[jq] ? p * 0.125f : -1e9f;
    }
    __syncthreads();

    // ---- softmax: one lane per row ----
    if (t < 32) {
        int r = t;
        float mx = -1e9f;
#pragma unroll
        for (int jj = 0; jj < 15; jj++) mx = fmaxf(mx, sc[r][jj]);
        int uni = (mx == -1e9f);
        suni[r] = uni;
        float e[15], den = 0.f;
#pragma unroll
        for (int jj = 0; jj < 15; jj++) {
            e[jj] = uni ? 0.f : expf(sc[r][jj] - mx);
            den += e[jj];
        }
        float inv = uni ? 0.f : 1.f / den;
#pragma unroll
        for (int jj = 0; jj < 15; jj++) sc[r][jj] = e[jj] * inv;
    }
    __syncthreads();

    // ---- w write: 32 rows x 1024 cols, coalesced float4, streaming ----
    const float invS = 1.0f / (float)S_;
    float* wbase = out_w + (size_t)bh * S_ * S_ + (size_t)i0 * S_;
#pragma unroll
    for (int p = 0; p < 16; p++) {
        int idx = p * 512 + t;
        int r = idx >> 8, c = (idx & 255) * 4;
        int jb = i0 + r - KHALF;     // global col of band start for this row
        float4 val;
        if (suni[r]) {
            val = make_float4(invS, invS, invS, invS);
        } else {
            float* vv = (float*)&val;
#pragma unroll
            for (int u = 0; u < 4; u++) {
                int jj = c + u - jb;
                int jjc = min(max(jj, 0), 14);
                float sv = sc[r][jjc];
                vv[u] = (jj >= 0 && jj < 15) ? sv : 0.f;
            }
        }
        __stwt((float4*)(wbase + (size_t)r * S_ + c), val);
    }

    // ---- r output: out_m = feats + sum_jj w * v ----
#pragma unroll
    for (int p = 0; p < 4; p++) {
        int idx = p * 512 + t;
        int r = idx >> 6, d = idx & 63;
        float acc;
        if (suni[r]) {
            acc = g_vsum[b * OD_ + h * HD_ + d] * invS;
        } else {
            acc = 0.f;
#pragma unroll
            for (int jj = 0; jj < 15; jj++)
                acc = fmaf(sc[r][jj], svt[d][r + jj], acc);
        }
        size_t oidx = (size_t)(b * S_ + i0 + r) * OD_ + h * HD_ + d;
        out_m[oidx] = feats[oidx] + acc;
    }
}

// ---------------------------------------------------------------------------
extern "C" void kernel_launch(void* const* d_in, const int* in_sizes, int n_in,
                              void* d_out, int out_size)
{
    const float* feats = (const float*)d_in[0];
    const int*   mask  = (const int*)  d_in[1];
    const float* Wc    = (const float*)d_in[2];
    const float* bc    = (const float*)d_in[3];
    const float* Wv    = (const float*)d_in[4];
    const float* bv    = (const float*)d_in[5];

    float* out   = (float*)d_out;
    float* out_m = out;
    float* out_w = out + (size_t)B_ * S_ * OD_;

    static int smem_set = 0;
    if (!smem_set) {
        cudaFuncSetAttribute(gemm_tc, cudaFuncAttributeMaxDynamicSharedMemorySize, GEMM_SMEM);
        smem_set = 1;
    }

    conv_A<<<(M_ * ID_ / 4) / 256, 256>>>(feats);
    conv_W<<<dim3(NT_ / 32, ID_ / 32), dim3(32, 8)>>>(Wc, Wv);
    bias_k<<<(B_ * OD_) / 256, 256>>>(bc, bv);
    gemm_tc<<<dim3(NT_ / 128, M_ / 128), 128, GEMM_SMEM>>>();
    attn2_kernel<<<B_ * H_ * (S_ / TI), 512>>>(feats, mask, out_m, out_w);
}

// round 14
// speedup vs baseline: 3.7119x; 1.0128x over previous
#include <cuda_runtime.h>
#include <cuda_fp16.h>
#include <math.h>
#include <stdint.h>

// Problem constants
#define B_   8
#define S_   1024
#define ID_  1024
#define OD_  1024
#define H_   16
#define HD_  64
#define M_   8192          // B*S rows
#define NT_  3072          // q(1024) | v(1024) | k(1024) fused N
#define KHALF 7
#define TI   32            // attention rows per block

// ---------------- device scratch (no allocations allowed) -------------------
__device__ __align__(128) __half g_Ah[(size_t)M_ * ID_];
__device__ __align__(128) __half g_Al[(size_t)M_ * ID_];
__device__ __align__(128) __half g_Wt[(size_t)NT_ * ID_];    // W^T fp16 [n][k]
__device__ float g_bias[NT_];
__device__ __align__(128) float g_qvk[(size_t)M_ * NT_];     // [row][ q | v | k ]
__device__ float g_vsum[B_ * OD_];

// ---------------- PTX helpers (sm_80/90 portable only) ----------------------
__device__ __forceinline__ uint32_t smem_u32(const void* p) {
    uint32_t a;
    asm("{ .reg .u64 t; cvta.to.shared.u64 t, %1; cvt.u32.u64 %0, t; }" : "=r"(a) : "l"(p));
    return a;
}
__device__ __forceinline__ void cp_async16(uint32_t dst, const void* src) {
    asm volatile("cp.async.cg.shared.global [%0], [%1], 16;" :: "r"(dst), "l"(src));
}
#define CP_COMMIT() asm volatile("cp.async.commit_group;" ::: "memory")

__device__ __forceinline__ void ldsm4(uint32_t* r, uint32_t addr) {
    asm volatile("ldmatrix.sync.aligned.m8n8.x4.shared.b16 {%0,%1,%2,%3}, [%4];"
        : "=r"(r[0]), "=r"(r[1]), "=r"(r[2]), "=r"(r[3]) : "r"(addr));
}
__device__ __forceinline__ void mma_f16(float* c, const uint32_t* a, const uint32_t* b) {
    asm volatile("mma.sync.aligned.m16n8k16.row.col.f32.f16.f16.f32 "
        "{%0,%1,%2,%3}, {%4,%5,%6,%7}, {%8,%9}, {%0,%1,%2,%3};"
        : "+f"(c[0]), "+f"(c[1]), "+f"(c[2]), "+f"(c[3])
        : "r"(a[0]), "r"(a[1]), "r"(a[2]), "r"(a[3]), "r"(b[0]), "r"(b[1]));
}

// ---------------------------------------------------------------------------
// Fused prep: conv_A | conv_W | bias+vsum-seed, dispatched by blockIdx.x.
//   [0, 8192)        conv_A: 256 float4 per block
//   [8192, 11264)    conv_W: 32x32 tile transpose (3072 tiles)
//   [11264, 11296)   bias table + vsum seed
// ---------------------------------------------------------------------------
#define PREP_CONVW_BASE 8192
#define PREP_BIAS_BASE  11264
#define PREP_BLOCKS     11296

__global__ __launch_bounds__(256) void prep_kernel(
    const float* __restrict__ A,
    const float* __restrict__ Wc, const float* __restrict__ Wv,
    const float* __restrict__ bc, const float* __restrict__ bv)
{
    const int bx = blockIdx.x;
    const int t  = threadIdx.x;

    if (bx < PREP_CONVW_BASE) {
        // ---- conv_A: fp32 -> fp16 hi/lo ----
        size_t idx = (size_t)bx * 256 + t;
        float4 a = ((const float4*)A)[idx];
        float v[4] = {a.x, a.y, a.z, a.w};
        __half h[4], l[4];
#pragma unroll
        for (int j = 0; j < 4; j++) {
            h[j] = __float2half_rn(v[j]);
            l[j] = __float2half_rn(v[j] - __half2float(h[j]));
        }
        ((uint2*)g_Ah)[idx] = *(uint2*)h;
        ((uint2*)g_Al)[idx] = *(uint2*)l;
    } else if (bx < PREP_BIAS_BASE) {
        // ---- conv_W: transpose + fp16 round ----
        __shared__ float ts[32][33];
        int tile = bx - PREP_CONVW_BASE;        // 0..3071
        int n0 = (tile % 96) * 32, k0 = (tile / 96) * 32;
        int tx = t & 31, ty = t >> 5;
#pragma unroll
        for (int j = 0; j < 32; j += 8) {
            int k = k0 + ty + j, n = n0 + tx;
            float val = (n < 2 * OD_) ? Wc[(size_t)k * (2 * OD_) + n]
                                      : Wv[(size_t)k * OD_ + (n - 2 * OD_)];
            ts[ty + j][tx] = val;
        }
        __syncthreads();
#pragma unroll
        for (int j = 0; j < 32; j += 8) {
            float val = ts[tx][ty + j];
            size_t o = (size_t)(n0 + ty + j) * ID_ + (k0 + tx);
            g_Wt[o] = __float2half_rn(val);
        }
    } else {
        // ---- bias table + vsum seed (vsum = 1024 * v-bias; gemm atomics add)
        int i = (bx - PREP_BIAS_BASE) * 256 + t;   // 0..8191
        if (i < NT_) g_bias[i] = (i < 2 * OD_) ? bc[i] : bv[i - 2 * OD_];
        int od = i & (OD_ - 1);
        g_vsum[i] = 1024.f * bc[OD_ + od];
    }
}

// ---------------------------------------------------------------------------
// HMMA GEMM: fp16x2 split (A hi/lo, W single). CTA 128x128, BK=32, 4 buffers,
// one load + wait_group 2 + one sync per chunk. 4 warps (2x2), tile 64x64.
// Inner loop interleaves ldsm with MMA per m-tile (lower frag pressure).
// v-region CTAs accumulate column sums into g_vsum (fused vsum).
// ---------------------------------------------------------------------------
#define AH_OFF 0
#define AL_OFF 8192
#define BF_OFF 16384
#define STAGE_SZ 24576
#define NSTAGE 4
#define GEMM_SMEM (NSTAGE * STAGE_SZ)
#define NCHUNK 32

__device__ __forceinline__ uint32_t tile_off(int row, int chunk) {
    return (uint32_t)(row * 64 + (((chunk ^ ((row >> 1) & 3)) & 3) << 4));
}

__device__ __forceinline__ void load_chunk(uint32_t stage, int m0, int n0, int c, int tid)
{
    const int k0 = c * 32;
    const char* srcs[3] = {
        (const char*)g_Ah + ((size_t)m0 * ID_ + k0) * 2,
        (const char*)g_Al + ((size_t)m0 * ID_ + k0) * 2,
        (const char*)g_Wt + ((size_t)n0 * ID_ + k0) * 2
    };
    const uint32_t offs[3] = {AH_OFF, AL_OFF, BF_OFF};
#pragma unroll
    for (int mi = 0; mi < 3; mi++) {
        const char* s = srcs[mi];
        uint32_t dbase = stage + offs[mi];
#pragma unroll
        for (int it = 0; it < 4; it++) {
            int e = tid + it * 128;          // 0..511
            int row = e >> 2, chunk = e & 3;
            cp_async16(dbase + tile_off(row, chunk), s + (size_t)row * 2048 + chunk * 16);
        }
    }
}

extern "C" __global__ void __launch_bounds__(128, 2) gemm_tc()
{
    extern __shared__ char smem[];
    const uint32_t sb = smem_u32(smem);
    const int tid = threadIdx.x, wid = tid >> 5, lane = tid & 31;
    const int n0 = blockIdx.x * 128, m0 = blockIdx.y * 128;
    const int wm = wid >> 1, wn = wid & 1;          // 2 x 2 warp grid, tile 64x64

    float acc[4][8][4];
#pragma unroll
    for (int a = 0; a < 4; a++)
#pragma unroll
        for (int b = 0; b < 8; b++)
#pragma unroll
            for (int d = 0; d < 4; d++) acc[a][b][d] = 0.f;

    const int a_row = wm * 64 + (lane & 15);
    const int a_sel = lane >> 4;
    const int b_n   = wn * 64 + ((lane >> 4) & 1) * 8 + (lane & 7);
    const int b_sel = (lane >> 3) & 1;

    // prologue: chunks 0,1,2 into buffers 0,1,2
    load_chunk(sb + 0 * STAGE_SZ, m0, n0, 0, tid); CP_COMMIT();
    load_chunk(sb + 1 * STAGE_SZ, m0, n0, 1, tid); CP_COMMIT();
    load_chunk(sb + 2 * STAGE_SZ, m0, n0, 2, tid); CP_COMMIT();

    uint32_t buf = 0;

    for (int c = 0; c < NCHUNK; c++) {
        const int rem = NCHUNK - 1 - c;
        if (rem >= 2)      asm volatile("cp.async.wait_group 2;" ::: "memory");
        else if (rem == 1) asm volatile("cp.async.wait_group 1;" ::: "memory");
        else               asm volatile("cp.async.wait_group 0;" ::: "memory");
        __syncthreads();   // chunk c resident + all warps done with c-1

        if (c + 3 < NCHUNK) {
            uint32_t nbuf = buf + 3; if (nbuf >= NSTAGE) nbuf -= NSTAGE;
            load_chunk(sb + nbuf * STAGE_SZ, m0, n0, c + 3, tid);
            CP_COMMIT();
        }

        const uint32_t stage = sb + buf * STAGE_SZ;
#pragma unroll
        for (int ks = 0; ks < 2; ks++) {
            uint32_t bf[4][4];
#pragma unroll
            for (int nt = 0; nt < 4; nt++) {
                int n = b_n + nt * 16, ch = ks * 2 + b_sel;
                ldsm4(bf[nt], stage + BF_OFF + tile_off(n, ch));
            }
#pragma unroll
            for (int mt = 0; mt < 4; mt++) {
                uint32_t ah[4], al[4];
                int row = a_row + mt * 16, ch = ks * 2 + a_sel;
                ldsm4(ah, stage + AH_OFF + tile_off(row, ch));
                ldsm4(al, stage + AL_OFF + tile_off(row, ch));
#pragma unroll
                for (int ng = 0; ng < 8; ng++) {
                    uint32_t b2[2] = { bf[ng >> 1][(ng & 1) * 2], bf[ng >> 1][(ng & 1) * 2 + 1] };
                    mma_f16(acc[mt][ng], ah, b2);
                    mma_f16(acc[mt][ng], al, b2);
                }
            }
        }

        buf++; if (buf >= NSTAGE) buf -= NSTAGE;
    }

    // epilogue: write acc + bias to g_qvk
    const int g  = lane >> 2;
    const int tc = (lane & 3) * 2;
    const int m0w = m0 + wm * 64, n0w = n0 + wn * 64;
#pragma unroll
    for (int mt = 0; mt < 4; mt++) {
#pragma unroll
        for (int r2 = 0; r2 < 2; r2++) {
            int row = m0w + mt * 16 + g + r2 * 8;
            float* orow = g_qvk + (size_t)row * NT_ + n0w;
#pragma unroll
            for (int ng = 0; ng < 8; ng++) {
                int col = ng * 8 + tc;
                float2 o;
                o.x = acc[mt][ng][r2 * 2 + 0] + g_bias[n0w + col];
                o.y = acc[mt][ng][r2 * 2 + 1] + g_bias[n0w + col + 1];
                *(float2*)(orow + col) = o;
            }
        }
    }

    // fused vsum: v-region CTAs accumulate column sums (dots only; bias seeded)
    if (n0 >= OD_ && n0 < 2 * OD_) {
        const int bb = m0 >> 10;   // batch index
#pragma unroll
        for (int ng = 0; ng < 8; ng++) {
            float s0 = 0.f, s1 = 0.f;
#pragma unroll
            for (int mt = 0; mt < 4; mt++) {
                s0 += acc[mt][ng][0] + acc[mt][ng][2];
                s1 += acc[mt][ng][1] + acc[mt][ng][3];
            }
            // reduce across the 8 row-groups (lanes with same lane&3)
#pragma unroll
            for (int off = 16; off >= 4; off >>= 1) {
                s0 += __shfl_xor_sync(0xffffffffu, s0, off);
                s1 += __shfl_xor_sync(0xffffffffu, s1, off);
            }
            if (lane < 4) {
                int col = n0w - OD_ + ng * 8 + lane * 2;
                atomicAdd(&g_vsum[bb * OD_ + col],     s0);
                atomicAdd(&g_vsum[bb * OD_ + col + 1], s1);
            }
        }
    }
}

// ---------------------------------------------------------------------------
// Banded attention v2: block-tiled. One 512-thread block per (b, h, 32 rows).
// ---------------------------------------------------------------------------
__global__ __launch_bounds__(512) void attn2_kernel(
    const float* __restrict__ feats,
    const int*   __restrict__ mask,
    float* __restrict__ out_m,
    float* __restrict__ out_w)
{
    __shared__ float skt[64][33];     // k transposed  [d][r]
    __shared__ float sqt[64][49];     // q transposed  [d][jq]
    __shared__ float svt[64][49];     // v transposed  [d][jq]
    __shared__ float sc[32][17];      // scores/weights [r][jj]
    __shared__ int   svalid[48];
    __shared__ int   suni[32];

    const int t    = threadIdx.x;
    const int blk  = blockIdx.x;          // (b*H + h)*(S/TI) + tile
    const int tile = blk & 31;
    const int bh   = blk >> 5;
    const int h    = bh & (H_ - 1);
    const int b    = bh >> 4;
    const int i0   = tile * TI;
    const int jlo  = i0 - KHALF;

    const float* qvk_b = g_qvk + (size_t)(b * S_) * NT_;

    // ---- load k (32 rows), transposed ----
    {
        int r = t >> 4, d0 = (t & 15) * 4;
        float4 kv = *(const float4*)(qvk_b + (size_t)(i0 + r) * NT_ + 2 * OD_ + h * HD_ + d0);
        skt[d0 + 0][r] = kv.x; skt[d0 + 1][r] = kv.y;
        skt[d0 + 2][r] = kv.z; skt[d0 + 3][r] = kv.w;
    }
    // ---- load q, v band (46 rows), transposed; zero OOB ----
    for (int e = t; e < 46 * 16; e += 512) {
        int jq = e >> 4, d0 = (e & 15) * 4;
        int j = jlo + jq;
        float4 qv = make_float4(0.f, 0.f, 0.f, 0.f);
        float4 vv = make_float4(0.f, 0.f, 0.f, 0.f);
        if (j >= 0 && j < S_) {
            qv = *(const float4*)(qvk_b + (size_t)j * NT_ + h * HD_ + d0);
            vv = *(const float4*)(qvk_b + (size_t)j * NT_ + OD_ + h * HD_ + d0);
        }
        sqt[d0 + 0][jq] = qv.x; sqt[d0 + 1][jq] = qv.y;
        sqt[d0 + 2][jq] = qv.z; sqt[d0 + 3][jq] = qv.w;
        svt[d0 + 0][jq] = vv.x; svt[d0 + 1][jq] = vv.y;
        svt[d0 + 2][jq] = vv.z; svt[d0 + 3][jq] = vv.w;
    }
    if (t < 48) {
        int j = jlo + t;
        svalid[t] = (j >= 0 && j < S_) ? (mask[b * S_ + j] != 0) : 0;
    }
    __syncthreads();

    // ---- scores: thread (r, jj) does a full 64-d dot from smem ----
    if (t < 480) {
        int r = t & 31, jj = t >> 5, jq = r + jj;
        float p0 = 0.f, p1 = 0.f, p2 = 0.f, p3 = 0.f;
#pragma unroll
        for (int d = 0; d < 64; d += 4) {
            p0 = fmaf(skt[d + 0][r], sqt[d + 0][jq], p0);
            p1 = fmaf(skt[d + 1][r], sqt[d + 1][jq], p1);
            p2 = fmaf(skt[d + 2][r], sqt[d + 2][jq], p2);
            p3 = fmaf(skt[d + 3][r], sqt[d + 3][jq], p3);
        }
        float p = (p0 + p1) + (p2 + p3);
        sc[r][jj] = svalid[jq] ? p * 0.125f : -1e9f;
    }
    __syncthreads();

    // ---- softmax: one lane per row ----
    if (t < 32) {
        int r = t;
        float mx = -1e9f;
#pragma unroll
        for (int jj = 0; jj < 15; jj++) mx = fmaxf(mx, sc[r][jj]);
        int uni = (mx == -1e9f);
        suni[r] = uni;
        float e[15], den = 0.f;
#pragma unroll
        for (int jj = 0; jj < 15; jj++) {
            e[jj] = uni ? 0.f : expf(sc[r][jj] - mx);
            den += e[jj];
        }
        float inv = uni ? 0.f : 1.f / den;
#pragma unroll
        for (int jj = 0; jj < 15; jj++) sc[r][jj] = e[jj] * inv;
    }
    __syncthreads();

    // ---- w write: 32 rows x 1024 cols, coalesced float4, streaming ----
    const float invS = 1.0f / (float)S_;
    float* wbase = out_w + (size_t)bh * S_ * S_ + (size_t)i0 * S_;
#pragma unroll
    for (int p = 0; p < 16; p++) {
        int idx = p * 512 + t;
        int r = idx >> 8, c = (idx & 255) * 4;
        int jb = i0 + r - KHALF;     // global col of band start for this row
        float4 val;
        if (suni[r]) {
            val = make_float4(invS, invS, invS, invS);
        } else {
            float* vv = (float*)&val;
#pragma unroll
            for (int u = 0; u < 4; u++) {
                int jj = c + u - jb;
                int jjc = min(max(jj, 0), 14);
                float sv = sc[r][jjc];
                vv[u] = (jj >= 0 && jj < 15) ? sv : 0.f;
            }
        }
        __stwt((float4*)(wbase + (size_t)r * S_ + c), val);
    }

    // ---- r output: out_m = feats + sum_jj w * v ----
#pragma unroll
    for (int p = 0; p < 4; p++) {
        int idx = p * 512 + t;
        int r = idx >> 6, d = idx & 63;
        float acc;
        if (suni[r]) {
            acc = g_vsum[b * OD_ + h * HD_ + d] * invS;
        } else {
            acc = 0.f;
#pragma unroll
            for (int jj = 0; jj < 15; jj++)
                acc = fmaf(sc[r][jj], svt[d][r + jj], acc);
        }
        size_t oidx = (size_t)(b * S_ + i0 + r) * OD_ + h * HD_ + d;
        out_m[oidx] = feats[oidx] + acc;
    }
}

// ---------------------------------------------------------------------------
extern "C" void kernel_launch(void* const* d_in, const int* in_sizes, int n_in,
                              void* d_out, int out_size)
{
    const float* feats = (const float*)d_in[0];
    const int*   mask  = (const int*)  d_in[1];
    const float* Wc    = (const float*)d_in[2];
    const float* bc    = (const float*)d_in[3];
    const float* Wv    = (const float*)d_in[4];
    const float* bv    = (const float*)d_in[5];

    float* out   = (float*)d_out;
    float* out_m = out;
    float* out_w = out + (size_t)B_ * S_ * OD_;

    static int smem_set = 0;
    if (!smem_set) {
        cudaFuncSetAttribute(gemm_tc, cudaFuncAttributeMaxDynamicSharedMemorySize, GEMM_SMEM);
        smem_set = 1;
    }

    prep_kernel<<<PREP_BLOCKS, 256>>>(feats, Wc, Wv, bc, bv);
    gemm_tc<<<dim3(NT_ / 128, M_ / 128), 128, GEMM_SMEM>>>();
    attn2_kernel<<<B_ * H_ * (S_ / TI), 512>>>(feats, mask, out_m, out_w);
}

// round 17
// speedup vs baseline: 4.9682x; 1.3385x over previous
#include <cuda_runtime.h>
#include <cuda_fp16.h>
#include <math.h>
#include <stdint.h>

// Problem constants
#define B_   8
#define S_   1024
#define ID_  1024
#define OD_  1024
#define H_   16
#define HD_  64
#define M_   8192          // B*S rows
#define NT_  3072          // q(1024) | v(1024) | k(1024) fused N
#define KHALF 7
#define TI   32            // attention rows per block

// ---------------- device scratch (no allocations allowed) -------------------
__device__ __align__(128) __half g_Ah[(size_t)M_ * ID_];
__device__ __align__(128) __half g_Wt[(size_t)NT_ * ID_];    // W^T fp16 [n][k]
__device__ float g_bias[NT_];
__device__ __align__(128) float g_qvk[(size_t)M_ * NT_];     // [row][ q | v | k ]
__device__ float g_vsum[B_ * OD_];

// ---------------- PTX helpers (sm_80/90 portable only) ----------------------
__device__ __forceinline__ uint32_t smem_u32(const void* p) {
    uint32_t a;
    asm("{ .reg .u64 t; cvta.to.shared.u64 t, %1; cvt.u32.u64 %0, t; }" : "=r"(a) : "l"(p));
    return a;
}
__device__ __forceinline__ void cp_async16(uint32_t dst, const void* src) {
    asm volatile("cp.async.cg.shared.global [%0], [%1], 16;" :: "r"(dst), "l"(src));
}
#define CP_COMMIT() asm volatile("cp.async.commit_group;" ::: "memory")

__device__ __forceinline__ void ldsm4(uint32_t* r, uint32_t addr) {
    asm volatile("ldmatrix.sync.aligned.m8n8.x4.shared.b16 {%0,%1,%2,%3}, [%4];"
        : "=r"(r[0]), "=r"(r[1]), "=r"(r[2]), "=r"(r[3]) : "r"(addr));
}
__device__ __forceinline__ void mma_f16(float* c, const uint32_t* a, const uint32_t* b) {
    asm volatile("mma.sync.aligned.m16n8k16.row.col.f32.f16.f16.f32 "
        "{%0,%1,%2,%3}, {%4,%5,%6,%7}, {%8,%9}, {%0,%1,%2,%3};"
        : "+f"(c[0]), "+f"(c[1]), "+f"(c[2]), "+f"(c[3])
        : "r"(a[0]), "r"(a[1]), "r"(a[2]), "r"(a[3]), "r"(b[0]), "r"(b[1]));
}

// ---------------------------------------------------------------------------
// Fused prep: conv_A | conv_W | bias+vsum-seed, dispatched by blockIdx.x.
//   [0, 8192)        conv_A: 256 float4 per block -> fp16
//   [8192, 11264)    conv_W: 32x32 tile transpose (3072 tiles)
//   [11264, 11296)   bias table + vsum seed
// ---------------------------------------------------------------------------
#define PREP_CONVW_BASE 8192
#define PREP_BIAS_BASE  11264
#define PREP_BLOCKS     11296

__global__ __launch_bounds__(256) void prep_kernel(
    const float* __restrict__ A,
    const float* __restrict__ Wc, const float* __restrict__ Wv,
    const float* __restrict__ bc, const float* __restrict__ bv)
{
    const int bx = blockIdx.x;
    const int t  = threadIdx.x;

    if (bx < PREP_CONVW_BASE) {
        // ---- conv_A: fp32 -> fp16 ----
        size_t idx = (size_t)bx * 256 + t;
        float4 a = ((const float4*)A)[idx];
        __half h[4];
        h[0] = __float2half_rn(a.x);
        h[1] = __float2half_rn(a.y);
        h[2] = __float2half_rn(a.z);
        h[3] = __float2half_rn(a.w);
        ((uint2*)g_Ah)[idx] = *(uint2*)h;
    } else if (bx < PREP_BIAS_BASE) {
        // ---- conv_W: transpose + fp16 round ----
        __shared__ float ts[32][33];
        int tile = bx - PREP_CONVW_BASE;        // 0..3071
        int n0 = (tile % 96) * 32, k0 = (tile / 96) * 32;
        int tx = t & 31, ty = t >> 5;
#pragma unroll
        for (int j = 0; j < 32; j += 8) {
            int k = k0 + ty + j, n = n0 + tx;
            float val = (n < 2 * OD_) ? Wc[(size_t)k * (2 * OD_) + n]
                                      : Wv[(size_t)k * OD_ + (n - 2 * OD_)];
            ts[ty + j][tx] = val;
        }
        __syncthreads();
#pragma unroll
        for (int j = 0; j < 32; j += 8) {
            float val = ts[tx][ty + j];
            size_t o = (size_t)(n0 + ty + j) * ID_ + (k0 + tx);
            g_Wt[o] = __float2half_rn(val);
        }
    } else {
        // ---- bias table + vsum seed (vsum = 1024 * v-bias; gemm atomics add)
        int i = (bx - PREP_BIAS_BASE) * 256 + t;   // 0..8191
        if (i < NT_) g_bias[i] = (i < 2 * OD_) ? bc[i] : bv[i - 2 * OD_];
        int od = i & (OD_ - 1);
        g_vsum[i] = 1024.f * bc[OD_ + od];
    }
}

// ---------------------------------------------------------------------------
// HMMA GEMM: single fp16 (A and W rounded). CTA 128x128, BK=32, 4 buffers,
// one load + wait_group 2 + one sync per chunk. 4 warps (2x2), tile 64x64.
// 64KB smem + reduced regs -> target 3 CTAs/SM.
// v-region CTAs accumulate column sums into g_vsum (fused vsum).
// ---------------------------------------------------------------------------
#define AH_OFF 0
#define BF_OFF 8192
#define STAGE_SZ 16384
#define NSTAGE 4
#define GEMM_SMEM (NSTAGE * STAGE_SZ)
#define NCHUNK 32

__device__ __forceinline__ uint32_t tile_off(int row, int chunk) {
    return (uint32_t)(row * 64 + (((chunk ^ ((row >> 1) & 3)) & 3) << 4));
}

__device__ __forceinline__ void load_chunk(uint32_t stage, int m0, int n0, int c, int tid)
{
    const int k0 = c * 32;
    const char* srcs[2] = {
        (const char*)g_Ah + ((size_t)m0 * ID_ + k0) * 2,
        (const char*)g_Wt + ((size_t)n0 * ID_ + k0) * 2
    };
    const uint32_t offs[2] = {AH_OFF, BF_OFF};
#pragma unroll
    for (int mi = 0; mi < 2; mi++) {
        const char* s = srcs[mi];
        uint32_t dbase = stage + offs[mi];
#pragma unroll
        for (int it = 0; it < 4; it++) {
            int e = tid + it * 128;          // 0..511
            int row = e >> 2, chunk = e & 3;
            cp_async16(dbase + tile_off(row, chunk), s + (size_t)row * 2048 + chunk * 16);
        }
    }
}

extern "C" __global__ void __launch_bounds__(128, 3) gemm_tc()
{
    extern __shared__ char smem[];
    const uint32_t sb = smem_u32(smem);
    const int tid = threadIdx.x, wid = tid >> 5, lane = tid & 31;
    const int n0 = blockIdx.x * 128, m0 = blockIdx.y * 128;
    const int wm = wid >> 1, wn = wid & 1;          // 2 x 2 warp grid, tile 64x64

    float acc[4][8][4];
#pragma unroll
    for (int a = 0; a < 4; a++)
#pragma unroll
        for (int b = 0; b < 8; b++)
#pragma unroll
            for (int d = 0; d < 4; d++) acc[a][b][d] = 0.f;

    const int a_row = wm * 64 + (lane & 15);
    const int a_sel = lane >> 4;
    const int b_n   = wn * 64 + ((lane >> 4) & 1) * 8 + (lane & 7);
    const int b_sel = (lane >> 3) & 1;

    // prologue: chunks 0,1,2 into buffers 0,1,2
    load_chunk(sb + 0 * STAGE_SZ, m0, n0, 0, tid); CP_COMMIT();
    load_chunk(sb + 1 * STAGE_SZ, m0, n0, 1, tid); CP_COMMIT();
    load_chunk(sb + 2 * STAGE_SZ, m0, n0, 2, tid); CP_COMMIT();

    uint32_t buf = 0;

    for (int c = 0; c < NCHUNK; c++) {
        const int rem = NCHUNK - 1 - c;
        if (rem >= 2)      asm volatile("cp.async.wait_group 2;" ::: "memory");
        else if (rem == 1) asm volatile("cp.async.wait_group 1;" ::: "memory");
        else               asm volatile("cp.async.wait_group 0;" ::: "memory");
        __syncthreads();   // chunk c resident + all warps done with c-1

        if (c + 3 < NCHUNK) {
            uint32_t nbuf = buf + 3; if (nbuf >= NSTAGE) nbuf -= NSTAGE;
            load_chunk(sb + nbuf * STAGE_SZ, m0, n0, c + 3, tid);
            CP_COMMIT();
        }

        const uint32_t stage = sb + buf * STAGE_SZ;
#pragma unroll
        for (int ks = 0; ks < 2; ks++) {
            uint32_t bf[4][4];
#pragma unroll
            for (int nt = 0; nt < 4; nt++) {
                int n = b_n + nt * 16, ch = ks * 2 + b_sel;
                ldsm4(bf[nt], stage + BF_OFF + tile_off(n, ch));
            }
#pragma unroll
            for (int mt = 0; mt < 4; mt++) {
                uint32_t ah[4];
                int row = a_row + mt * 16, ch = ks * 2 + a_sel;
                ldsm4(ah, stage + AH_OFF + tile_off(row, ch));
#pragma unroll
                for (int ng = 0; ng < 8; ng++) {
                    uint32_t b2[2] = { bf[ng >> 1][(ng & 1) * 2], bf[ng >> 1][(ng & 1) * 2 + 1] };
                    mma_f16(acc[mt][ng], ah, b2);
                }
            }
        }

        buf++; if (buf >= NSTAGE) buf -= NSTAGE;
    }

    // epilogue: write acc + bias to g_qvk
    const int g  = lane >> 2;
    const int tc = (lane & 3) * 2;
    const int m0w = m0 + wm * 64, n0w = n0 + wn * 64;
#pragma unroll
    for (int mt = 0; mt < 4; mt++) {
#pragma unroll
        for (int r2 = 0; r2 < 2; r2++) {
            int row = m0w + mt * 16 + g + r2 * 8;
            float* orow = g_qvk + (size_t)row * NT_ + n0w;
#pragma unroll
            for (int ng = 0; ng < 8; ng++) {
                int col = ng * 8 + tc;
                float2 o;
                o.x = acc[mt][ng][r2 * 2 + 0] + g_bias[n0w + col];
                o.y = acc[mt][ng][r2 * 2 + 1] + g_bias[n0w + col + 1];
                *(float2*)(orow + col) = o;
            }
        }
    }

    // fused vsum: v-region CTAs accumulate column sums (dots only; bias seeded)
    if (n0 >= OD_ && n0 < 2 * OD_) {
        const int bb = m0 >> 10;   // batch index
#pragma unroll
        for (int ng = 0; ng < 8; ng++) {
            float s0 = 0.f, s1 = 0.f;
#pragma unroll
            for (int mt = 0; mt < 4; mt++) {
                s0 += acc[mt][ng][0] + acc[mt][ng][2];
                s1 += acc[mt][ng][1] + acc[mt][ng][3];
            }
            // reduce across the 8 row-groups (lanes with same lane&3)
#pragma unroll
            for (int off = 16; off >= 4; off >>= 1) {
                s0 += __shfl_xor_sync(0xffffffffu, s0, off);
                s1 += __shfl_xor_sync(0xffffffffu, s1, off);
            }
            if (lane < 4) {
                int col = n0w - OD_ + ng * 8 + lane * 2;
                atomicAdd(&g_vsum[bb * OD_ + col],     s0);
                atomicAdd(&g_vsum[bb * OD_ + col + 1], s1);
            }
        }
    }
}

// ---------------------------------------------------------------------------
// Banded attention v2: block-tiled. One 512-thread block per (b, h, 32 rows).
// ---------------------------------------------------------------------------
__global__ __launch_bounds__(512) void attn2_kernel(
    const float* __restrict__ feats,
    const int*   __restrict__ mask,
    float* __restrict__ out_m,
    float* __restrict__ out_w)
{
    __shared__ float skt[64][33];     // k transposed  [d][r]
    __shared__ float sqt[64][49];     // q transposed  [d][jq]
    __shared__ float svt[64][49];     // v transposed  [d][jq]
    __shared__ float sc[32][17];      // scores/weights [r][jj]
    __shared__ int   svalid[48];
    __shared__ int   suni[32];

    const int t    = threadIdx.x;
    const int blk  = blockIdx.x;          // (b*H + h)*(S/TI) + tile
    const int tile = blk & 31;
    const int bh   = blk >> 5;
    const int h    = bh & (H_ - 1);
    const int b    = bh >> 4;
    const int i0   = tile * TI;
    const int jlo  = i0 - KHALF;

    const float* qvk_b = g_qvk + (size_t)(b * S_) * NT_;

    // ---- load k (32 rows), transposed ----
    {
        int r = t >> 4, d0 = (t & 15) * 4;
        float4 kv = *(const float4*)(qvk_b + (size_t)(i0 + r) * NT_ + 2 * OD_ + h * HD_ + d0);
        skt[d0 + 0][r] = kv.x; skt[d0 + 1][r] = kv.y;
        skt[d0 + 2][r] = kv.z; skt[d0 + 3][r] = kv.w;
    }
    // ---- load q, v band (46 rows), transposed; zero OOB ----
    for (int e = t; e < 46 * 16; e += 512) {
        int jq = e >> 4, d0 = (e & 15) * 4;
        int j = jlo + jq;
        float4 qv = make_float4(0.f, 0.f, 0.f, 0.f);
        float4 vv = make_float4(0.f, 0.f, 0.f, 0.f);
        if (j >= 0 && j < S_) {
            qv = *(const float4*)(qvk_b + (size_t)j * NT_ + h * HD_ + d0);
            vv = *(const float4*)(qvk_b + (size_t)j * NT_ + OD_ + h * HD_ + d0);
        }
        sqt[d0 + 0][jq] = qv.x; sqt[d0 + 1][jq] = qv.y;
        sqt[d0 + 2][jq] = qv.z; sqt[d0 + 3][jq] = qv.w;
        svt[d0 + 0][jq] = vv.x; svt[d0 + 1][jq] = vv.y;
        svt[d0 + 2][jq] = vv.z; svt[d0 + 3][jq] = vv.w;
    }
    if (t < 48) {
        int j = jlo + t;
        svalid[t] = (j >= 0 && j < S_) ? (mask[b * S_ + j] != 0) : 0;
    }
    __syncthreads();

    // ---- scores: thread (r, jj) does a full 64-d dot from smem ----
    if (t < 480) {
        int r = t & 31, jj = t >> 5, jq = r + jj;
        float p0 = 0.f, p1 = 0.f, p2 = 0.f, p3 = 0.f;
#pragma unroll
        for (int d = 0; d < 64; d += 4) {
            p0 = fmaf(skt[d + 0][r], sqt[d + 0][jq], p0);
            p1 = fmaf(skt[d + 1][r], sqt[d + 1][jq], p1);
            p2 = fmaf(skt[d + 2][r], sqt[d + 2][jq], p2);
            p3 = fmaf(skt[d + 3][r], sqt[d + 3][jq], p3);
        }
        float p = (p0 + p1) + (p2 + p3);
        sc[r][jj] = svalid[jq] ? p * 0.125f : -1e9f;
    }
    __syncthreads();

    // ---- softmax: one lane per row ----
    if (t < 32) {
        int r = t;
        float mx = -1e9f;
#pragma unroll
        for (int jj = 0; jj < 15; jj++) mx = fmaxf(mx, sc[r][jj]);
        int uni = (mx == -1e9f);
        suni[r] = uni;
        float e[15], den = 0.f;
#pragma unroll
        for (int jj = 0; jj < 15; jj++) {
            e[jj] = uni ? 0.f : expf(sc[r][jj] - mx);
            den += e[jj];
        }
        float inv = uni ? 0.f : 1.f / den;
#pragma unroll
        for (int jj = 0; jj < 15; jj++) sc[r][jj] = e[jj] * inv;
    }
    __syncthreads();

    // ---- w write: 32 rows x 1024 cols, coalesced float4, streaming ----
    const float invS = 1.0f / (float)S_;
    float* wbase = out_w + (size_t)bh * S_ * S_ + (size_t)i0 * S_;
#pragma unroll
    for (int p = 0; p < 16; p++) {
        int idx = p * 512 + t;
        int r = idx >> 8, c = (idx & 255) * 4;
        int jb = i0 + r - KHALF;     // global col of band start for this row
        float4 val;
        if (suni[r]) {
            val = make_float4(invS, invS, invS, invS);
        } else {
            float* vv = (float*)&val;
#pragma unroll
            for (int u = 0; u < 4; u++) {
                int jj = c + u - jb;
                int jjc = min(max(jj, 0), 14);
                float sv = sc[r][jjc];
                vv[u] = (jj >= 0 && jj < 15) ? sv : 0.f;
            }
        }
        __stwt((float4*)(wbase + (size_t)r * S_ + c), val);
    }

    // ---- r output: out_m = feats + sum_jj w * v ----
#pragma unroll
    for (int p = 0; p < 4; p++) {
        int idx = p * 512 + t;
        int r = idx >> 6, d = idx & 63;
        float acc;
        if (suni[r]) {
            acc = g_vsum[b * OD_ + h * HD_ + d] * invS;
        } else {
            acc = 0.f;
#pragma unroll
            for (int jj = 0; jj < 15; jj++)
                acc = fmaf(sc[r][jj], svt[d][r + jj], acc);
        }
        size_t oidx = (size_t)(b * S_ + i0 + r) * OD_ + h * HD_ + d;
        out_m[oidx] = feats[oidx] + acc;
    }
}

// ---------------------------------------------------------------------------
extern "C" void kernel_launch(void* const* d_in, const int* in_sizes, int n_in,
                              void* d_out, int out_size)
{
    const float* feats = (const float*)d_in[0];
    const int*   mask  = (const int*)  d_in[1];
    const float* Wc    = (const float*)d_in[2];
    const float* bc    = (const float*)d_in[3];
    const float* Wv    = (const float*)d_in[4];
    const float* bv    = (const float*)d_in[5];

    float* out   = (float*)d_out;
    float* out_m = out;
    float* out_w = out + (size_t)B_ * S_ * OD_;

    static int smem_set = 0;
    if (!smem_set) {
        cudaFuncSetAttribute(gemm_tc, cudaFuncAttributeMaxDynamicSharedMemorySize, GEMM_SMEM);
        smem_set = 1;
    }

    prep_kernel<<<PREP_BLOCKS, 256>>>(feats, Wc, Wv, bc, bv);
    gemm_tc<<<dim3(NT_ / 128, M_ / 128), 128, GEMM_SMEM>>>();
    attn2_kernel<<<B_ * H_ * (S_ / TI), 512>>>(feats, mask, out_m, out_w);
}